// round 9
// baseline (speedup 1.0000x reference)
#include <cuda_runtime.h>
#include <math.h>

// ---------------- problem constants ----------------
#define BSZ 512
#define DD 100
#define TOTAL_P 1086
#define NTH 256

// scratch buffer offsets (floats)
#define SCH1_L0 0ull            // [2][512*124][100]
#define SCH1_L1 12697600ull     // [2][512*19][100]
#define SCH0_L0 14643200ull     // [2][512*4][100]
#define SPEC0   15052800ull     // [2][512][100]
#define RAND_L0 15155200ull     // [512*4][100]
#define RVIEW   15360000ull     // [512][100]
#define SCRATCH_TOTAL 15411200ull

__device__ float g_buf[SCRATCH_TOTAL];

typedef unsigned long long ull;

__device__ __forceinline__ ull fma2(ull a, ull b, ull c) {
    ull d;
    asm("fma.rn.f32x2 %0, %1, %2, %3;" : "=l"(d) : "l"(a), "l"(b), "l"(c));
    return d;
}
__device__ __forceinline__ ull pack2(float a) {
    ull d;
    asm("mov.b64 %0, {%1, %1};" : "=l"(d) : "f"(a));
    return d;
}
__device__ __forceinline__ void unpack2(ull v, float& lo, float& hi) {
    asm("mov.b64 {%0, %1}, %2;" : "=f"(lo), "=f"(hi) : "l"(v));
}
__device__ __forceinline__ void cpasync16(unsigned dst, const void* src) {
    asm volatile("cp.async.ca.shared.global [%0], [%1], 16;" :: "r"(dst), "l"(src));
}
__device__ __forceinline__ void cpasync8(unsigned dst, const void* src) {
    asm volatile("cp.async.ca.shared.global [%0], [%1], 8;" :: "r"(dst), "l"(src));
}

// ================= GEMM-style aggregation kernel (L0 + L1 launches) =================
// 3 K-chunks (36/32/32); cp.async stages self-tile + W overlapped with mean build.
struct Job {
    const float* gsrc;
    float*       out;
    const float* Ws;
    const float* Wn;
    const int*   neigh;
    int mode;              // 0 = prev feats, 1 = type_embed, 2 = rw_embed
    int idx;
    int nseg;
    int s[5];
    int fan[4];
    int noff[5];
    int nb_b, nb_t;
    int Rout;
    int Rin;
    int rows;
    int blk0;
};
struct MultiParams {
    Job job[3];
    int njobs;
    const int* nodeids;
};

// shared layout (floats): A tiles stride 36
#define SM_AS   0               // [64*36] = 2304
#define SM_AM   2320            // 2304 + 16 pad
#define SM_W    4640            // [36*100] = 3600
#define SM_SELF 8240            // int[64]
#define SM_FAN  8304            // int[64]
#define SM_COFF 8368            // int[64*9]
#define SM_INVF 8944            // float[64]
#define SM_FLOATS 9008
#define AGG_SMEM_BYTES (SM_FLOATS * 4)

// 20 FFMA2 for one k-step: rows a0..a3 against w row (10 cols as 5 ull)
__device__ __forceinline__ void gstep(float a0, float a1, float a2, float a3,
                                      const float* wrow, ull acc[4][5]) {
    ull p0 = pack2(a0), p1 = pack2(a1), p2 = pack2(a2), p3 = pack2(a3);
    const ull* wp = (const ull*)wrow;
    ull w0 = wp[0], w1 = wp[1], w2 = wp[2], w3 = wp[3], w4 = wp[4];
    acc[0][0] = fma2(p0, w0, acc[0][0]); acc[0][1] = fma2(p0, w1, acc[0][1]);
    acc[0][2] = fma2(p0, w2, acc[0][2]); acc[0][3] = fma2(p0, w3, acc[0][3]);
    acc[0][4] = fma2(p0, w4, acc[0][4]);
    acc[1][0] = fma2(p1, w0, acc[1][0]); acc[1][1] = fma2(p1, w1, acc[1][1]);
    acc[1][2] = fma2(p1, w2, acc[1][2]); acc[1][3] = fma2(p1, w3, acc[1][3]);
    acc[1][4] = fma2(p1, w4, acc[1][4]);
    acc[2][0] = fma2(p2, w0, acc[2][0]); acc[2][1] = fma2(p2, w1, acc[2][1]);
    acc[2][2] = fma2(p2, w2, acc[2][2]); acc[2][3] = fma2(p2, w3, acc[2][3]);
    acc[2][4] = fma2(p2, w4, acc[2][4]);
    acc[3][0] = fma2(p3, w0, acc[3][0]); acc[3][1] = fma2(p3, w1, acc[3][1]);
    acc[3][2] = fma2(p3, w2, acc[3][2]); acc[3][3] = fma2(p3, w3, acc[3][3]);
    acc[3][4] = fma2(p3, w4, acc[3][4]);
}

__global__ __launch_bounds__(160, 6) void agg_multi_kernel(MultiParams p) {
    extern __shared__ float sm[];
    float* sAs  = sm + SM_AS;
    float* sAm  = sm + SM_AM;
    float* sW   = sm + SM_W;
    int*   sSelf = (int*)(sm + SM_SELF);
    int*   sFan  = (int*)(sm + SM_FAN);
    int*   sCoff = (int*)(sm + SM_COFF);
    float* sInvF = sm + SM_INVF;

    const int tid = threadIdx.x;

    int j = 0;
    if (p.njobs > 1 && (int)blockIdx.x >= p.job[1].blk0) j = 1;
    if (p.njobs > 2 && (int)blockIdx.x >= p.job[2].blk0) j = 2;
    Job jb = p.job[j];
    const int R0 = (blockIdx.x - jb.blk0) * 64;

    // ---- per-row metadata (once) ----
    if (tid < 64) {
        int R = R0 + tid;
        if (R >= jb.rows) R = jb.rows - 1;
        int t = (R >= jb.Rout) ? 1 : 0;
        int g = R - t * jb.Rout;
        int kk = 0, off = 0;
        while (kk + 1 < jb.nseg && g >= off + BSZ * jb.s[kk]) { off += BSZ * jb.s[kk]; kk++; }
        int local = g - off;
        int b = local / jb.s[kk];
        int i = local - b * jb.s[kk];
        int fan = jb.fan[kk];
        sFan[tid]  = fan;
        sInvF[tid] = 1.0f / (float)fan;
        int soff;
        if (jb.mode == 0) {
            soff = (t * jb.Rin + g) * DD;
        } else {
            int id = (kk == 0) ? p.nodeids[b]
                               : jb.neigh[b * jb.nb_b + t * jb.nb_t + jb.noff[kk] + i];
            soff = (jb.mode == 1) ? (id * 400 + t * 200 + jb.idx * 100) : id * DD;
        }
        sSelf[tid] = soff;
        if (jb.mode == 0) {
            int off2 = off + BSZ * jb.s[kk];
            int base = (t * jb.Rin + off2 + b * jb.s[kk + 1] + i * fan) * DD;
            for (int jj = 0; jj < fan; jj++) sCoff[tid * 9 + jj] = base + jj * DD;
        } else {
            int nb2 = b * jb.nb_b + t * jb.nb_t + jb.noff[kk + 1] + i * fan;
            for (int jj = 0; jj < fan; jj++) {
                int id = jb.neigh[nb2 + jj];
                sCoff[tid * 9 + jj] = (jb.mode == 1) ? (id * 400 + t * 200 + jb.idx * 100)
                                                     : id * DD;
            }
        }
    }

    // thread tile: rows {rt, rt+16, rt+32, rt+48}, cols [10ct, 10ct+10)
    const int ct = tid % 10, rt = tid / 10;
    const int c0 = ct * 10;

    ull acc[4][5];
#pragma unroll
    for (int r = 0; r < 4; r++)
#pragma unroll
        for (int q = 0; q < 5; q++) acc[r][q] = 0ull;

    const float* src = jb.gsrc;
    const unsigned sW_b  = (unsigned)__cvta_generic_to_shared(sW);
    const unsigned sAs_b = (unsigned)__cvta_generic_to_shared(sAs);

    // ---- three K-chunks: [0,36), [36,68), [68,100) ----
#pragma unroll 1
    for (int c = 0; c < 3; c++) {
        const int k0  = (c == 0) ? 0 : (c == 1 ? 36 : 68);
        const int nk  = (c == 0) ? 36 : 32;
        const int nk4 = nk / 4;

        __syncthreads();   // covers metadata on first pass, prior-chunk reads later

        // async-stage W chunk [nk][100] (8B pieces)
        {
            const float* Ws = jb.Ws;
            const float* Wn = jb.Wn;
            for (int e = tid; e < nk * 50; e += 160) {
                int k = e / 50, cc = (e - k * 50) * 2;
                const float* sp = (cc < 50) ? (Ws + (k0 + k) * 50 + cc)
                                            : (Wn + (k0 + k) * 50 + (cc - 50));
                cpasync8(sW_b + (unsigned)(k * 100 + cc) * 4u, sp);
            }
        }
        // async-stage self tile (16B pieces)
        for (int e = tid; e < 64 * nk4; e += 160) {
            int row = e / nk4, q = e - row * nk4;
            cpasync16(sAs_b + (unsigned)(row * 36 + 4 * q) * 4u,
                      src + sSelf[row] + k0 + 4 * q);
        }
        asm volatile("cp.async.commit_group;");

        // mean tile build (register path, overlaps the async copies)
        for (int e = tid; e < 64 * nk4; e += 160) {
            int row = e / nk4, q = e - row * nk4;
            int f = sFan[row];
            const int* co = sCoff + row * 9;
            float x = 0.f, y = 0.f, z = 0.f, w = 0.f;
#pragma unroll
            for (int jj = 0; jj < 9; jj++) {
                if (jj < f) {
                    float4 v = *(const float4*)(src + co[jj] + k0 + 4 * q);
                    x += v.x; y += v.y; z += v.z; w += v.w;
                }
            }
            float iv = sInvF[row];
            float4 r; r.x = x * iv; r.y = y * iv; r.z = z * iv; r.w = w * iv;
            *(float4*)&sAm[row * 36 + 4 * q] = r;
        }
        asm volatile("cp.async.wait_group 0;" ::: "memory");
        __syncthreads();

        const float* Ab = (ct < 5) ? sAs : sAm;
        const float* A0 = Ab + (rt +  0) * 36;
        const float* A1 = Ab + (rt + 16) * 36;
        const float* A2 = Ab + (rt + 32) * 36;
        const float* A3 = Ab + (rt + 48) * 36;

#pragma unroll 2
        for (int k = 0; k < nk; k += 4) {
            float4 a0 = *(const float4*)(A0 + k);
            float4 a1 = *(const float4*)(A1 + k);
            float4 a2 = *(const float4*)(A2 + k);
            float4 a3 = *(const float4*)(A3 + k);
            gstep(a0.x, a1.x, a2.x, a3.x, &sW[(k + 0) * 100 + c0], acc);
            gstep(a0.y, a1.y, a2.y, a3.y, &sW[(k + 1) * 100 + c0], acc);
            gstep(a0.z, a1.z, a2.z, a3.z, &sW[(k + 2) * 100 + c0], acc);
            gstep(a0.w, a1.w, a2.w, a3.w, &sW[(k + 3) * 100 + c0], acc);
        }
    }

#pragma unroll
    for (int r = 0; r < 4; r++) {
        int R = R0 + rt + 16 * r;
        if (R < jb.rows) {
            int t = (R >= jb.Rout) ? 1 : 0;
            int g = R - t * jb.Rout;
            float* op = jb.out + (size_t)(t * jb.Rout + g) * DD + c0;
#pragma unroll
            for (int q = 0; q < 5; q++) {
                float lo, hi;
                unpack2(acc[r][q], lo, hi);
                float2 o;
                o.x = fmaxf(lo, 0.f);
                o.y = fmaxf(hi, 0.f);
                *(float2*)(op + 2 * q) = o;
            }
        }
    }
}

// ================= fused small-tail kernel: sch1 L2+L3 + attention + final =================
#define TK_W    0
#define TK_F1   10000
#define TK_F2   11900
#define TK_M    12300
#define TK_SPEC 12800
#define TK_SCR  13400
#define TK_MISC 16400
#define TK_FLOATS 17000
#define TK_SMEM_BYTES (TK_FLOATS * 4)

__device__ __forceinline__ void load_W(float* W, const float* Ws, const float* Wn, int tid) {
    for (int e = tid; e < 5000; e += NTH) {
        int k = e / 50, c2 = (e - k * 50) * 2;
        float2 v;
        if (c2 < 50) v = *(const float2*)(Ws + k * 50 + c2);
        else         v = *(const float2*)(Wn + k * 50 + (c2 - 50));
        *(float2*)&W[k * 100 + c2] = v;
    }
}

__device__ __forceinline__ void do_level(
    const float* IN, float* OUT, float* M, const float* W,
    int nout, int O1, int O2, int O3, int F0, int F1, int F2, int tid)
{
    for (int it = tid; it < nout * 25; it += NTH) {
        int j = it / 25, k4 = (it - (it / 25) * 25) * 4;
        int k = (j >= O2) ? 2 : ((j >= O1) ? 1 : 0);
        int f  = (k == 0) ? F0 : (k == 1 ? F1 : F2);
        int o  = (k == 0) ? 0  : (k == 1 ? O1 : O2);
        int cs = (k == 0) ? O1 : (k == 1 ? O2 : O3);
        int cb = cs + (j - o) * f;
        float x = 0.f, y = 0.f, z = 0.f, w = 0.f;
        for (int i = 0; i < f; i++) {
            float4 v = *(const float4*)&IN[(cb + i) * 100 + k4];
            x += v.x; y += v.y; z += v.z; w += v.w;
        }
        float iv = 1.0f / (float)f;
        float4 r; r.x = x * iv; r.y = y * iv; r.z = z * iv; r.w = w * iv;
        *(float4*)&M[j * 100 + k4] = r;
    }
    __syncthreads();
    for (int it = tid; it < nout * 50; it += NTH) {
        int j = it / 50, cc = it - (it / 50) * 50;
        int h = cc / 25, c2 = cc - h * 25;
        int col = h * 50 + c2 * 2;
        const float* A = h ? (M + j * 100) : (IN + j * 100);
        ull acc = 0ull;
#pragma unroll 4
        for (int k = 0; k < 100; k++) {
            ull wv = *(const ull*)&W[k * 100 + col];
            acc = fma2(pack2(A[k]), wv, acc);
        }
        float lo, hi; unpack2(acc, lo, hi);
        OUT[j * 100 + col]     = fmaxf(lo, 0.f);
        OUT[j * 100 + col + 1] = fmaxf(hi, 0.f);
    }
    __syncthreads();
}

__device__ __forceinline__ void mha_stage(
    float* X, float* LNX, float* Q, float* K, float* V, float* O,
    float* mu, float* rs, float* SC, float* ATT,
    int nb, int na,
    const float* __restrict__ Wq, const float* __restrict__ Wk,
    const float* __restrict__ Wv, const float* __restrict__ Wf,
    const float* __restrict__ gam, const float* __restrict__ bet, int tid)
{
    if (tid < 6) {
        float s = 0.f;
        for (int d = 0; d < 100; d++) s += X[tid * 100 + d];
        float m = s * 0.01f;
        float v = 0.f;
        for (int d = 0; d < 100; d++) { float z = X[tid * 100 + d] - m; v += z * z; }
        mu[tid] = m;
        rs[tid] = rsqrtf(v * 0.01f + 1e-6f);
    }
    __syncthreads();
    for (int e = tid; e < 600; e += NTH) {
        int r = e / 100, d = e - r * 100;
        LNX[e] = (X[e] - mu[r]) * rs[r] * gam[d] + bet[d];
    }
    __syncthreads();
    if (tid < 100) {
        float aq[6], ak[6], av[6];
#pragma unroll
        for (int r = 0; r < 6; r++) { aq[r] = 0.f; ak[r] = 0.f; av[r] = 0.f; }
        for (int k2 = 0; k2 < 100; k2++) {
            float wq = Wq[k2 * 100 + tid];
            float wk = Wk[k2 * 100 + tid];
            float wv = Wv[k2 * 100 + tid];
#pragma unroll
            for (int r = 0; r < 6; r++) {
                aq[r] += LNX[r * 100 + k2] * wq;
                ak[r] += X[r * 100 + k2] * wk;
                av[r] += X[r * 100 + k2] * wv;
            }
        }
#pragma unroll
        for (int r = 0; r < 6; r++) {
            Q[r * 100 + tid] = aq[r];
            K[r * 100 + tid] = ak[r];
            V[r * 100 + tid] = av[r];
        }
    }
    __syncthreads();
    int nsc = nb * na * na;
    if (tid < nsc) {
        int bi = tid / (na * na), rem = tid - bi * na * na;
        int qa = rem / na, ka = rem - qa * na;
        const float* qp = Q + (bi * na + qa) * 100;
        const float* kp = K + (bi * na + ka) * 100;
        float s = 0.f;
        for (int d = 0; d < 100; d++) s += qp[d] * kp[d];
        SC[tid] = s * 0.1f;
    }
    __syncthreads();
    if (tid < nb * na) {
        int base = tid * na;
        float mx = -1e30f;
        for (int ka = 0; ka < na; ka++) mx = fmaxf(mx, SC[base + ka]);
        float ev[3], sum = 0.f;
        for (int ka = 0; ka < na; ka++) { ev[ka] = expf(SC[base + ka] - mx); sum += ev[ka]; }
        float inv = 1.0f / sum;
        for (int ka = 0; ka < na; ka++) ATT[base + ka] = ev[ka] * inv;
    }
    __syncthreads();
    if (tid < 100) {
        for (int bi = 0; bi < nb; bi++)
            for (int qa = 0; qa < na; qa++) {
                float acc = 0.f;
                for (int ka = 0; ka < na; ka++)
                    acc += ATT[(bi * na + qa) * na + ka] * V[(bi * na + ka) * 100 + tid];
                O[(bi * na + qa) * 100 + tid] = acc;
            }
    }
    __syncthreads();
    if (tid < 100) {
        float acc[6];
#pragma unroll
        for (int r = 0; r < 6; r++) acc[r] = 0.f;
        for (int k2 = 0; k2 < 100; k2++) {
            float wf = Wf[k2 * 100 + tid];
#pragma unroll
            for (int r = 0; r < 6; r++) acc[r] += O[r * 100 + k2] * wf;
        }
#pragma unroll
        for (int r = 0; r < 6; r++) X[r * 100 + tid] = acc[r] + X[r * 100 + tid];
    }
    __syncthreads();
}

__global__ __launch_bounds__(NTH) void tail_kernel(
    const float* __restrict__ sch1_l1,
    const float* __restrict__ spec0g, const float* __restrict__ rviewg,
    const float* __restrict__ agg1_self, const float* __restrict__ agg1_neigh,
    const int* __restrict__ edgetype, const int* __restrict__ nodeids,
    const float* __restrict__ base_embed, const float* __restrict__ reflect,
    const float* __restrict__ vWq, const float* __restrict__ vWk,
    const float* __restrict__ vWv, const float* __restrict__ vWf,
    const float* __restrict__ vg, const float* __restrict__ vb,
    const float* __restrict__ mWq, const float* __restrict__ mWk,
    const float* __restrict__ mWv, const float* __restrict__ mWf,
    const float* __restrict__ mg, const float* __restrict__ mb,
    float* __restrict__ outp)
{
    extern __shared__ float sm[];
    float* W    = sm + TK_W;
    float* F1   = sm + TK_F1;
    float* F2   = sm + TK_F2;
    float* M    = sm + TK_M;
    float* SPEC = sm + TK_SPEC;
    float* SCR  = sm + TK_SCR;
    float* MISC = sm + TK_MISC;

    const int b = blockIdx.x;
    const int tid = threadIdx.x;

    for (int t = 0; t < 2; t++) {
        const float* L1 = sch1_l1 + (size_t)t * (512 * 19) * 100;
        for (int e = tid; e < 19 * 25; e += NTH) {
            int row = e / 25, k4 = (e - (e / 25) * 25) * 4;
            int g;
            if (row == 0)      g = b;
            else if (row < 4)  g = 512 + b * 3 + (row - 1);
            else               g = 2048 + b * 15 + (row - 4);
            *(float4*)&F1[row * 100 + k4] = *(const float4*)&L1[(size_t)g * 100 + k4];
        }
        load_W(W, agg1_self + 10000, agg1_neigh + 10000, tid);
        __syncthreads();
        do_level(F1, F2, M, W, 4, 1, 4, 19, 3, 5, 0, tid);
        load_W(W, agg1_self + 15000, agg1_neigh + 15000, tid);
        __syncthreads();
        do_level(F2, SPEC + (2 + t) * 100, M, W, 1, 1, 999, 999, 3, 0, 0, tid);
    }
    for (int e = tid; e < 200; e += NTH) {
        int t = e / 100, d = e - t * 100;
        SPEC[t * 100 + d] = spec0g[(size_t)(t * BSZ + b) * 100 + d];
    }
    for (int e = tid; e < 100; e += NTH) {
        float v = rviewg[(size_t)b * 100 + e];
        SPEC[4 * 100 + e] = v;
        SPEC[5 * 100 + e] = v;
    }
    __syncthreads();

    float* X   = SPEC;
    float* LNX = SCR;
    float* Q   = SCR + 600;
    float* K   = SCR + 1200;
    float* V   = SCR + 1800;
    float* O   = SCR + 2400;
    float* TMP = F1;
    float* mu  = MISC;
    float* rs  = MISC + 8;
    float* SC  = MISC + 16;
    float* ATT = MISC + 48;
    float* SEL = MISC + 80;
    float* RES = MISC + 192;
    float* part = MISC + 400;

    mha_stage(X, LNX, Q, K, V, O, mu, rs, SC, ATT, 3, 2, vWq, vWk, vWv, vWf, vg, vb, tid);

    for (int e = tid; e < 600; e += NTH) TMP[e] = X[e];
    __syncthreads();
    for (int e = tid; e < 600; e += NTH) {
        int r = e / 100, d = e - r * 100;
        int t = r / 3, v = r - t * 3;
        X[e] = TMP[(v * 2 + t) * 100 + d];
    }
    __syncthreads();

    mha_stage(X, LNX, Q, K, V, O, mu, rs, SC, ATT, 2, 3, mWq, mWk, mWv, mWf, mg, mb, tid);

    const int typ = edgetype[BSZ + b];
    if (tid < 100) {
        SEL[tid] = (X[(typ * 3 + 0) * 100 + tid] +
                    X[(typ * 3 + 1) * 100 + tid] +
                    X[(typ * 3 + 2) * 100 + tid]) * (1.0f / 3.0f);
    }
    __syncthreads();

    const int node = nodeids[b];
    for (int o = tid; o < 200; o += NTH) {
        float acc = 0.f;
        const float* rp = reflect + (size_t)typ * 100 * 200 + o;
        for (int d = 0; d < 100; d++) acc += SEL[d] * rp[d * 200];
        RES[o] = base_embed[(size_t)node * 200 + o] + acc;
    }
    __syncthreads();
    float ps = 0.f;
    for (int o = tid; o < 200; o += NTH) ps += RES[o] * RES[o];
    part[tid % 128] = 0.f;
    __syncthreads();
    atomicAdd(&part[tid % 128], ps);
    __syncthreads();
    if (tid == 0) {
        float s = 0.f;
        for (int i = 0; i < 128; i++) s += part[i];
        part[0] = 1.0f / fmaxf(sqrtf(s), 1e-12f);
    }
    __syncthreads();
    float inv = part[0];
    for (int o = tid; o < 200; o += NTH) outp[(size_t)b * 200 + o] = RES[o] * inv;
}

// ---------------- host launcher ----------------
static void set_job(Job& j, const float* gsrc, float* out, const float* Ws, const float* Wn,
                    const int* neigh, int mode, int idx, int nseg,
                    const int* s, const int* fan, const int* noff,
                    int nb_b, int nb_t, int Rout, int Rin, int Tj, int blk0) {
    j.gsrc = gsrc; j.out = out; j.Ws = Ws; j.Wn = Wn; j.neigh = neigh;
    j.mode = mode; j.idx = idx; j.nseg = nseg;
    for (int i = 0; i < 5; i++) j.s[i] = s[i];
    for (int i = 0; i < 4; i++) j.fan[i] = fan[i];
    for (int i = 0; i < 5; i++) j.noff[i] = noff[i];
    j.nb_b = nb_b; j.nb_t = nb_t; j.Rout = Rout; j.Rin = Rin;
    j.rows = Rout * Tj; j.blk0 = blk0;
}

extern "C" void kernel_launch(void* const* d_in, const int* in_sizes, int n_in,
                              void* d_out, int out_size) {
    const int*   nodeids    = (const int*)d_in[0];
    const int*   edgetype   = (const int*)d_in[1];
    const int*   neighbors  = (const int*)d_in[2];
    const int*   rneigh     = (const int*)d_in[3];
    const float* base_embed = (const float*)d_in[4];
    const float* type_embed = (const float*)d_in[5];
    const float* rw_embed   = (const float*)d_in[6];
    const float* reflect    = (const float*)d_in[7];
    const float* agg0_self  = (const float*)d_in[8];
    const float* agg0_neigh = (const float*)d_in[9];
    const float* agg1_self  = (const float*)d_in[10];
    const float* agg1_neigh = (const float*)d_in[11];
    const float* rand_self  = (const float*)d_in[12];
    const float* rand_neighw= (const float*)d_in[13];
    const float* vWq = (const float*)d_in[14];
    const float* vWk = (const float*)d_in[15];
    const float* vWv = (const float*)d_in[16];
    const float* vWf = (const float*)d_in[17];
    const float* vg  = (const float*)d_in[18];
    const float* vb  = (const float*)d_in[19];
    const float* mWq = (const float*)d_in[20];
    const float* mWk = (const float*)d_in[21];
    const float* mWv = (const float*)d_in[22];
    const float* mWf = (const float*)d_in[23];
    const float* mg  = (const float*)d_in[24];
    const float* mb  = (const float*)d_in[25];
    float* outp = (float*)d_out;

    float* buf = nullptr;
    cudaGetSymbolAddress((void**)&buf, g_buf);

    cudaFuncSetAttribute(agg_multi_kernel,
                         cudaFuncAttributeMaxDynamicSharedMemorySize, AGG_SMEM_BYTES);
    cudaFuncSetAttribute(tail_kernel,
                         cudaFuncAttributeMaxDynamicSharedMemorySize, TK_SMEM_BYTES);

    const int s1[5]  = {1, 3, 15, 105, 945};
    const int f1[4]  = {3, 5, 7, 9};
    const int no1[5] = {0, 18, 21, 36, 141};
    const int s1b[5] = {1, 3, 15, 105, 0};
    const int f1b[4] = {3, 5, 7, 0};
    const int s0[5]  = {1, 3, 15, 0, 0};
    const int f0[4]  = {3, 5, 0, 0};
    const int no0[5] = {0, 0, 3, 0, 0};
    const int sT[5]  = {1, 3, 0, 0, 0};
    const int fT[4]  = {3, 0, 0, 0};
    const int noZ[5] = {0, 0, 0, 0, 0};

    MultiParams p;
    p.nodeids = nodeids;

    // ===== launch 1: all level-0 jobs =====
    {
        int b0 = 0;
        set_job(p.job[0], type_embed, buf + SCH1_L0, agg1_self, agg1_neigh, neighbors,
                1, 1, 4, s1, f1, no1, 2 * TOTAL_P, TOTAL_P, BSZ * 124, 0, 2, b0);
        b0 += (p.job[0].rows + 63) / 64;
        set_job(p.job[1], type_embed, buf + SCH0_L0, agg0_self, agg0_neigh, neighbors,
                1, 0, 2, s0, f0, no0, 2 * TOTAL_P, TOTAL_P, BSZ * 4, 0, 2, b0);
        b0 += (p.job[1].rows + 63) / 64;
        set_job(p.job[2], rw_embed, buf + RAND_L0, rand_self, rand_neighw, rneigh,
                2, 0, 2, s0, f0, no0, 18, 0, BSZ * 4, 0, 1, b0);
        b0 += (p.job[2].rows + 63) / 64;
        p.njobs = 3;
        agg_multi_kernel<<<b0, 160, AGG_SMEM_BYTES>>>(p);
    }
    // ===== launch 2: all level-1 jobs =====
    {
        int b0 = 0;
        set_job(p.job[0], buf + SCH1_L0, buf + SCH1_L1, agg1_self + 5000, agg1_neigh + 5000,
                nullptr, 0, 0, 3, s1b, f1b, noZ, 0, 0, BSZ * 19, BSZ * 124, 2, b0);
        b0 += (p.job[0].rows + 63) / 64;
        set_job(p.job[1], buf + SCH0_L0, buf + SPEC0, agg0_self + 5000, agg0_neigh + 5000,
                nullptr, 0, 0, 1, sT, fT, noZ, 0, 0, BSZ, BSZ * 4, 2, b0);
        b0 += (p.job[1].rows + 63) / 64;
        set_job(p.job[2], buf + RAND_L0, buf + RVIEW, rand_self + 5000, rand_neighw + 5000,
                nullptr, 0, 0, 1, sT, fT, noZ, 0, 0, BSZ, BSZ * 4, 1, b0);
        b0 += (p.job[2].rows + 63) / 64;
        p.njobs = 3;
        agg_multi_kernel<<<b0, 160, AGG_SMEM_BYTES>>>(p);
    }

    // ===== launch 3: fused tail =====
    tail_kernel<<<BSZ, NTH, TK_SMEM_BYTES>>>(
        buf + SCH1_L1, buf + SPEC0, buf + RVIEW,
        agg1_self, agg1_neigh,
        edgetype, nodeids, base_embed, reflect,
        vWq, vWk, vWv, vWf, vg, vb,
        mWq, mWk, mWv, mWf, mg, mb,
        outp);
}

// round 10
// speedup vs baseline: 1.2595x; 1.2595x over previous
#include <cuda_runtime.h>
#include <math.h>

// ---------------- problem constants ----------------
#define BSZ 512
#define DD 100
#define TOTAL_P 1086
#define NTH 256

// scratch buffer offsets (floats)
#define SCH1_L0 0ull            // [2][512*124][100]
#define SCH1_L1 12697600ull     // [2][512*19][100]
#define SCH0_L0 14643200ull     // [2][512*4][100]
#define SPEC0   15052800ull     // [2][512][100]
#define RAND_L0 15155200ull     // [512*4][100]
#define RVIEW   15360000ull     // [512][100]
#define SCRATCH_TOTAL 15411200ull

__device__ float g_buf[SCRATCH_TOTAL];

typedef unsigned long long ull;

__device__ __forceinline__ ull fma2(ull a, ull b, ull c) {
    ull d;
    asm("fma.rn.f32x2 %0, %1, %2, %3;" : "=l"(d) : "l"(a), "l"(b), "l"(c));
    return d;
}
__device__ __forceinline__ ull pack2(float a) {
    ull d;
    asm("mov.b64 %0, {%1, %1};" : "=l"(d) : "f"(a));
    return d;
}
__device__ __forceinline__ void unpack2(ull v, float& lo, float& hi) {
    asm("mov.b64 {%0, %1}, %2;" : "=f"(lo), "=f"(hi) : "l"(v));
}

// ================= GEMM-style aggregation kernel (L0 + L1 launches) =================
// 3 K-chunks (36/32/32); merged self+mean staging loop for high MLP.
struct Job {
    const float* gsrc;
    float*       out;
    const float* Ws;
    const float* Wn;
    const int*   neigh;
    int mode;              // 0 = prev feats, 1 = type_embed, 2 = rw_embed
    int idx;
    int nseg;
    int s[5];
    int fan[4];
    int noff[5];
    int nb_b, nb_t;
    int Rout;
    int Rin;
    int rows;
    int blk0;
};
struct MultiParams {
    Job job[3];
    int njobs;
    const int* nodeids;
};

// shared layout (floats): A tiles stride 36
#define SM_AS   0               // [64*36] = 2304
#define SM_AM   2320            // 2304 + 16 pad
#define SM_W    4640            // [36*100] = 3600
#define SM_SELF 8240            // int[64]
#define SM_FAN  8304            // int[64]
#define SM_COFF 8368            // int[64*9]
#define SM_INVF 8944            // float[64]
#define SM_FLOATS 9008
#define AGG_SMEM_BYTES (SM_FLOATS * 4)

// 20 FFMA2 for one k-step: rows a0..a3 against w row (10 cols as 5 ull)
__device__ __forceinline__ void gstep(float a0, float a1, float a2, float a3,
                                      const float* wrow, ull acc[4][5]) {
    ull p0 = pack2(a0), p1 = pack2(a1), p2 = pack2(a2), p3 = pack2(a3);
    const ull* wp = (const ull*)wrow;
    ull w0 = wp[0], w1 = wp[1], w2 = wp[2], w3 = wp[3], w4 = wp[4];
    acc[0][0] = fma2(p0, w0, acc[0][0]); acc[0][1] = fma2(p0, w1, acc[0][1]);
    acc[0][2] = fma2(p0, w2, acc[0][2]); acc[0][3] = fma2(p0, w3, acc[0][3]);
    acc[0][4] = fma2(p0, w4, acc[0][4]);
    acc[1][0] = fma2(p1, w0, acc[1][0]); acc[1][1] = fma2(p1, w1, acc[1][1]);
    acc[1][2] = fma2(p1, w2, acc[1][2]); acc[1][3] = fma2(p1, w3, acc[1][3]);
    acc[1][4] = fma2(p1, w4, acc[1][4]);
    acc[2][0] = fma2(p2, w0, acc[2][0]); acc[2][1] = fma2(p2, w1, acc[2][1]);
    acc[2][2] = fma2(p2, w2, acc[2][2]); acc[2][3] = fma2(p2, w3, acc[2][3]);
    acc[2][4] = fma2(p2, w4, acc[2][4]);
    acc[3][0] = fma2(p3, w0, acc[3][0]); acc[3][1] = fma2(p3, w1, acc[3][1]);
    acc[3][2] = fma2(p3, w2, acc[3][2]); acc[3][3] = fma2(p3, w3, acc[3][3]);
    acc[3][4] = fma2(p3, w4, acc[3][4]);
}

__global__ __launch_bounds__(160, 5) void agg_multi_kernel(MultiParams p) {
    extern __shared__ float sm[];
    float* sAs  = sm + SM_AS;
    float* sAm  = sm + SM_AM;
    float* sW   = sm + SM_W;
    int*   sSelf = (int*)(sm + SM_SELF);
    int*   sFan  = (int*)(sm + SM_FAN);
    int*   sCoff = (int*)(sm + SM_COFF);
    float* sInvF = sm + SM_INVF;

    const int tid = threadIdx.x;

    int j = 0;
    if (p.njobs > 1 && (int)blockIdx.x >= p.job[1].blk0) j = 1;
    if (p.njobs > 2 && (int)blockIdx.x >= p.job[2].blk0) j = 2;
    Job jb = p.job[j];
    const int R0 = (blockIdx.x - jb.blk0) * 64;

    // ---- per-row metadata (once) ----
    if (tid < 64) {
        int R = R0 + tid;
        if (R >= jb.rows) R = jb.rows - 1;
        int t = (R >= jb.Rout) ? 1 : 0;
        int g = R - t * jb.Rout;
        int kk = 0, off = 0;
        while (kk + 1 < jb.nseg && g >= off + BSZ * jb.s[kk]) { off += BSZ * jb.s[kk]; kk++; }
        int local = g - off;
        int b = local / jb.s[kk];
        int i = local - b * jb.s[kk];
        int fan = jb.fan[kk];
        sFan[tid]  = fan;
        sInvF[tid] = 1.0f / (float)fan;
        int soff;
        if (jb.mode == 0) {
            soff = (t * jb.Rin + g) * DD;
        } else {
            int id = (kk == 0) ? p.nodeids[b]
                               : jb.neigh[b * jb.nb_b + t * jb.nb_t + jb.noff[kk] + i];
            soff = (jb.mode == 1) ? (id * 400 + t * 200 + jb.idx * 100) : id * DD;
        }
        sSelf[tid] = soff;
        if (jb.mode == 0) {
            int off2 = off + BSZ * jb.s[kk];
            int base = (t * jb.Rin + off2 + b * jb.s[kk + 1] + i * fan) * DD;
            for (int jj = 0; jj < fan; jj++) sCoff[tid * 9 + jj] = base + jj * DD;
        } else {
            int nb2 = b * jb.nb_b + t * jb.nb_t + jb.noff[kk + 1] + i * fan;
            for (int jj = 0; jj < fan; jj++) {
                int id = jb.neigh[nb2 + jj];
                sCoff[tid * 9 + jj] = (jb.mode == 1) ? (id * 400 + t * 200 + jb.idx * 100)
                                                     : id * DD;
            }
        }
    }

    // thread tile: rows {rt, rt+16, rt+32, rt+48}, cols [10ct, 10ct+10)
    const int ct = tid % 10, rt = tid / 10;
    const int c0 = ct * 10;

    ull acc[4][5];
#pragma unroll
    for (int r = 0; r < 4; r++)
#pragma unroll
        for (int q = 0; q < 5; q++) acc[r][q] = 0ull;

    const float* src = jb.gsrc;

    // ---- three K-chunks: [0,36), [36,68), [68,100) ----
#pragma unroll 1
    for (int c = 0; c < 3; c++) {
        const int k0  = (c == 0) ? 0 : (c == 1 ? 36 : 68);
        const int nk  = (c == 0) ? 36 : 32;
        const int nk4 = nk / 4;
        const int nItems = 64 * nk4;   // 576 or 512 (<= 640)

        __syncthreads();   // covers metadata on first pass, prior-chunk reads later

        // stage W chunk [nk][100]
        {
            const float* Ws = jb.Ws;
            const float* Wn = jb.Wn;
            for (int e = tid; e < nk * 50; e += 160) {
                int k = e / 50, cc = (e - k * 50) * 2;
                float2 v;
                if (cc < 50) v = *(const float2*)(Ws + (k0 + k) * 50 + cc);
                else         v = *(const float2*)(Wn + (k0 + k) * 50 + (cc - 50));
                *(float2*)&sW[k * 100 + cc] = v;
            }
        }
        // merged self+mean staging: self LDG issued first, mean gathers in flight
        // behind it; stores after all loads -> MLP ~10 (x2 with unroll)
#pragma unroll 2
        for (int i = 0; i < 4; i++) {
            int e = tid + i * 160;
            bool ok = e < nItems;
            int row, q;
            if (ok) { row = e / nk4; q = e - row * nk4; }
            else    { row = 0; q = 0; }
            float4 sv = *(const float4*)(src + sSelf[row] + k0 + 4 * q);
            int f = sFan[row];
            const int* co = sCoff + row * 9;
            float x = 0.f, y = 0.f, z = 0.f, w = 0.f;
#pragma unroll
            for (int jj = 0; jj < 9; jj++) {
                if (jj < f) {
                    float4 v = *(const float4*)(src + co[jj] + k0 + 4 * q);
                    x += v.x; y += v.y; z += v.z; w += v.w;
                }
            }
            if (ok) {
                *(float4*)&sAs[row * 36 + 4 * q] = sv;
                float iv = sInvF[row];
                float4 r; r.x = x * iv; r.y = y * iv; r.z = z * iv; r.w = w * iv;
                *(float4*)&sAm[row * 36 + 4 * q] = r;
            }
        }
        __syncthreads();

        const float* Ab = (ct < 5) ? sAs : sAm;
        const float* A0 = Ab + (rt +  0) * 36;
        const float* A1 = Ab + (rt + 16) * 36;
        const float* A2 = Ab + (rt + 32) * 36;
        const float* A3 = Ab + (rt + 48) * 36;

#pragma unroll 2
        for (int k = 0; k < nk; k += 4) {
            float4 a0 = *(const float4*)(A0 + k);
            float4 a1 = *(const float4*)(A1 + k);
            float4 a2 = *(const float4*)(A2 + k);
            float4 a3 = *(const float4*)(A3 + k);
            gstep(a0.x, a1.x, a2.x, a3.x, &sW[(k + 0) * 100 + c0], acc);
            gstep(a0.y, a1.y, a2.y, a3.y, &sW[(k + 1) * 100 + c0], acc);
            gstep(a0.z, a1.z, a2.z, a3.z, &sW[(k + 2) * 100 + c0], acc);
            gstep(a0.w, a1.w, a2.w, a3.w, &sW[(k + 3) * 100 + c0], acc);
        }
    }

#pragma unroll
    for (int r = 0; r < 4; r++) {
        int R = R0 + rt + 16 * r;
        if (R < jb.rows) {
            int t = (R >= jb.Rout) ? 1 : 0;
            int g = R - t * jb.Rout;
            float* op = jb.out + (size_t)(t * jb.Rout + g) * DD + c0;
#pragma unroll
            for (int q = 0; q < 5; q++) {
                float lo, hi;
                unpack2(acc[r][q], lo, hi);
                float2 o;
                o.x = fmaxf(lo, 0.f);
                o.y = fmaxf(hi, 0.f);
                *(float2*)(op + 2 * q) = o;
            }
        }
    }
}

// ================= fused small-tail kernel: sch1 L2+L3 + attention + final =================
#define TK_W    0
#define TK_F1   10000
#define TK_F2   11900
#define TK_M    12300
#define TK_SPEC 12800
#define TK_SCR  13400
#define TK_MISC 16400
#define TK_FLOATS 17000
#define TK_SMEM_BYTES (TK_FLOATS * 4)

__device__ __forceinline__ void load_W(float* W, const float* Ws, const float* Wn, int tid) {
    for (int e = tid; e < 5000; e += NTH) {
        int k = e / 50, c2 = (e - k * 50) * 2;
        float2 v;
        if (c2 < 50) v = *(const float2*)(Ws + k * 50 + c2);
        else         v = *(const float2*)(Wn + k * 50 + (c2 - 50));
        *(float2*)&W[k * 100 + c2] = v;
    }
}

__device__ __forceinline__ void do_level(
    const float* IN, float* OUT, float* M, const float* W,
    int nout, int O1, int O2, int O3, int F0, int F1, int F2, int tid)
{
    for (int it = tid; it < nout * 25; it += NTH) {
        int j = it / 25, k4 = (it - (it / 25) * 25) * 4;
        int k = (j >= O2) ? 2 : ((j >= O1) ? 1 : 0);
        int f  = (k == 0) ? F0 : (k == 1 ? F1 : F2);
        int o  = (k == 0) ? 0  : (k == 1 ? O1 : O2);
        int cs = (k == 0) ? O1 : (k == 1 ? O2 : O3);
        int cb = cs + (j - o) * f;
        float x = 0.f, y = 0.f, z = 0.f, w = 0.f;
        for (int i = 0; i < f; i++) {
            float4 v = *(const float4*)&IN[(cb + i) * 100 + k4];
            x += v.x; y += v.y; z += v.z; w += v.w;
        }
        float iv = 1.0f / (float)f;
        float4 r; r.x = x * iv; r.y = y * iv; r.z = z * iv; r.w = w * iv;
        *(float4*)&M[j * 100 + k4] = r;
    }
    __syncthreads();
    for (int it = tid; it < nout * 50; it += NTH) {
        int j = it / 50, cc = it - (it / 50) * 50;
        int h = cc / 25, c2 = cc - h * 25;
        int col = h * 50 + c2 * 2;
        const float* A = h ? (M + j * 100) : (IN + j * 100);
        ull acc = 0ull;
#pragma unroll 4
        for (int k = 0; k < 100; k++) {
            ull wv = *(const ull*)&W[k * 100 + col];
            acc = fma2(pack2(A[k]), wv, acc);
        }
        float lo, hi; unpack2(acc, lo, hi);
        OUT[j * 100 + col]     = fmaxf(lo, 0.f);
        OUT[j * 100 + col + 1] = fmaxf(hi, 0.f);
    }
    __syncthreads();
}

__device__ __forceinline__ void mha_stage(
    float* X, float* LNX, float* Q, float* K, float* V, float* O,
    float* mu, float* rs, float* SC, float* ATT,
    int nb, int na,
    const float* __restrict__ Wq, const float* __restrict__ Wk,
    const float* __restrict__ Wv, const float* __restrict__ Wf,
    const float* __restrict__ gam, const float* __restrict__ bet, int tid)
{
    if (tid < 6) {
        float s = 0.f;
        for (int d = 0; d < 100; d++) s += X[tid * 100 + d];
        float m = s * 0.01f;
        float v = 0.f;
        for (int d = 0; d < 100; d++) { float z = X[tid * 100 + d] - m; v += z * z; }
        mu[tid] = m;
        rs[tid] = rsqrtf(v * 0.01f + 1e-6f);
    }
    __syncthreads();
    for (int e = tid; e < 600; e += NTH) {
        int r = e / 100, d = e - r * 100;
        LNX[e] = (X[e] - mu[r]) * rs[r] * gam[d] + bet[d];
    }
    __syncthreads();
    if (tid < 100) {
        float aq[6], ak[6], av[6];
#pragma unroll
        for (int r = 0; r < 6; r++) { aq[r] = 0.f; ak[r] = 0.f; av[r] = 0.f; }
        for (int k2 = 0; k2 < 100; k2++) {
            float wq = Wq[k2 * 100 + tid];
            float wk = Wk[k2 * 100 + tid];
            float wv = Wv[k2 * 100 + tid];
#pragma unroll
            for (int r = 0; r < 6; r++) {
                aq[r] += LNX[r * 100 + k2] * wq;
                ak[r] += X[r * 100 + k2] * wk;
                av[r] += X[r * 100 + k2] * wv;
            }
        }
#pragma unroll
        for (int r = 0; r < 6; r++) {
            Q[r * 100 + tid] = aq[r];
            K[r * 100 + tid] = ak[r];
            V[r * 100 + tid] = av[r];
        }
    }
    __syncthreads();
    int nsc = nb * na * na;
    if (tid < nsc) {
        int bi = tid / (na * na), rem = tid - bi * na * na;
        int qa = rem / na, ka = rem - qa * na;
        const float* qp = Q + (bi * na + qa) * 100;
        const float* kp = K + (bi * na + ka) * 100;
        float s = 0.f;
        for (int d = 0; d < 100; d++) s += qp[d] * kp[d];
        SC[tid] = s * 0.1f;
    }
    __syncthreads();
    if (tid < nb * na) {
        int base = tid * na;
        float mx = -1e30f;
        for (int ka = 0; ka < na; ka++) mx = fmaxf(mx, SC[base + ka]);
        float ev[3], sum = 0.f;
        for (int ka = 0; ka < na; ka++) { ev[ka] = expf(SC[base + ka] - mx); sum += ev[ka]; }
        float inv = 1.0f / sum;
        for (int ka = 0; ka < na; ka++) ATT[base + ka] = ev[ka] * inv;
    }
    __syncthreads();
    if (tid < 100) {
        for (int bi = 0; bi < nb; bi++)
            for (int qa = 0; qa < na; qa++) {
                float acc = 0.f;
                for (int ka = 0; ka < na; ka++)
                    acc += ATT[(bi * na + qa) * na + ka] * V[(bi * na + ka) * 100 + tid];
                O[(bi * na + qa) * 100 + tid] = acc;
            }
    }
    __syncthreads();
    if (tid < 100) {
        float acc[6];
#pragma unroll
        for (int r = 0; r < 6; r++) acc[r] = 0.f;
        for (int k2 = 0; k2 < 100; k2++) {
            float wf = Wf[k2 * 100 + tid];
#pragma unroll
            for (int r = 0; r < 6; r++) acc[r] += O[r * 100 + k2] * wf;
        }
#pragma unroll
        for (int r = 0; r < 6; r++) X[r * 100 + tid] = acc[r] + X[r * 100 + tid];
    }
    __syncthreads();
}

__global__ __launch_bounds__(NTH) void tail_kernel(
    const float* __restrict__ sch1_l1,
    const float* __restrict__ spec0g, const float* __restrict__ rviewg,
    const float* __restrict__ agg1_self, const float* __restrict__ agg1_neigh,
    const int* __restrict__ edgetype, const int* __restrict__ nodeids,
    const float* __restrict__ base_embed, const float* __restrict__ reflect,
    const float* __restrict__ vWq, const float* __restrict__ vWk,
    const float* __restrict__ vWv, const float* __restrict__ vWf,
    const float* __restrict__ vg, const float* __restrict__ vb,
    const float* __restrict__ mWq, const float* __restrict__ mWk,
    const float* __restrict__ mWv, const float* __restrict__ mWf,
    const float* __restrict__ mg, const float* __restrict__ mb,
    float* __restrict__ outp)
{
    extern __shared__ float sm[];
    float* W    = sm + TK_W;
    float* F1   = sm + TK_F1;
    float* F2   = sm + TK_F2;
    float* M    = sm + TK_M;
    float* SPEC = sm + TK_SPEC;
    float* SCR  = sm + TK_SCR;
    float* MISC = sm + TK_MISC;

    const int b = blockIdx.x;
    const int tid = threadIdx.x;

    for (int t = 0; t < 2; t++) {
        const float* L1 = sch1_l1 + (size_t)t * (512 * 19) * 100;
        for (int e = tid; e < 19 * 25; e += NTH) {
            int row = e / 25, k4 = (e - (e / 25) * 25) * 4;
            int g;
            if (row == 0)      g = b;
            else if (row < 4)  g = 512 + b * 3 + (row - 1);
            else               g = 2048 + b * 15 + (row - 4);
            *(float4*)&F1[row * 100 + k4] = *(const float4*)&L1[(size_t)g * 100 + k4];
        }
        load_W(W, agg1_self + 10000, agg1_neigh + 10000, tid);
        __syncthreads();
        do_level(F1, F2, M, W, 4, 1, 4, 19, 3, 5, 0, tid);
        load_W(W, agg1_self + 15000, agg1_neigh + 15000, tid);
        __syncthreads();
        do_level(F2, SPEC + (2 + t) * 100, M, W, 1, 1, 999, 999, 3, 0, 0, tid);
    }
    for (int e = tid; e < 200; e += NTH) {
        int t = e / 100, d = e - t * 100;
        SPEC[t * 100 + d] = spec0g[(size_t)(t * BSZ + b) * 100 + d];
    }
    for (int e = tid; e < 100; e += NTH) {
        float v = rviewg[(size_t)b * 100 + e];
        SPEC[4 * 100 + e] = v;
        SPEC[5 * 100 + e] = v;
    }
    __syncthreads();

    float* X   = SPEC;
    float* LNX = SCR;
    float* Q   = SCR + 600;
    float* K   = SCR + 1200;
    float* V   = SCR + 1800;
    float* O   = SCR + 2400;
    float* TMP = F1;
    float* mu  = MISC;
    float* rs  = MISC + 8;
    float* SC  = MISC + 16;
    float* ATT = MISC + 48;
    float* SEL = MISC + 80;
    float* RES = MISC + 192;
    float* part = MISC + 400;

    mha_stage(X, LNX, Q, K, V, O, mu, rs, SC, ATT, 3, 2, vWq, vWk, vWv, vWf, vg, vb, tid);

    for (int e = tid; e < 600; e += NTH) TMP[e] = X[e];
    __syncthreads();
    for (int e = tid; e < 600; e += NTH) {
        int r = e / 100, d = e - r * 100;
        int t = r / 3, v = r - t * 3;
        X[e] = TMP[(v * 2 + t) * 100 + d];
    }
    __syncthreads();

    mha_stage(X, LNX, Q, K, V, O, mu, rs, SC, ATT, 2, 3, mWq, mWk, mWv, mWf, mg, mb, tid);

    const int typ = edgetype[BSZ + b];
    if (tid < 100) {
        SEL[tid] = (X[(typ * 3 + 0) * 100 + tid] +
                    X[(typ * 3 + 1) * 100 + tid] +
                    X[(typ * 3 + 2) * 100 + tid]) * (1.0f / 3.0f);
    }
    __syncthreads();

    const int node = nodeids[b];
    for (int o = tid; o < 200; o += NTH) {
        float acc = 0.f;
        const float* rp = reflect + (size_t)typ * 100 * 200 + o;
        for (int d = 0; d < 100; d++) acc += SEL[d] * rp[d * 200];
        RES[o] = base_embed[(size_t)node * 200 + o] + acc;
    }
    __syncthreads();
    float ps = 0.f;
    for (int o = tid; o < 200; o += NTH) ps += RES[o] * RES[o];
    part[tid % 128] = 0.f;
    __syncthreads();
    atomicAdd(&part[tid % 128], ps);
    __syncthreads();
    if (tid == 0) {
        float s = 0.f;
        for (int i = 0; i < 128; i++) s += part[i];
        part[0] = 1.0f / fmaxf(sqrtf(s), 1e-12f);
    }
    __syncthreads();
    float inv = part[0];
    for (int o = tid; o < 200; o += NTH) outp[(size_t)b * 200 + o] = RES[o] * inv;
}

// ---------------- host launcher ----------------
static void set_job(Job& j, const float* gsrc, float* out, const float* Ws, const float* Wn,
                    const int* neigh, int mode, int idx, int nseg,
                    const int* s, const int* fan, const int* noff,
                    int nb_b, int nb_t, int Rout, int Rin, int Tj, int blk0) {
    j.gsrc = gsrc; j.out = out; j.Ws = Ws; j.Wn = Wn; j.neigh = neigh;
    j.mode = mode; j.idx = idx; j.nseg = nseg;
    for (int i = 0; i < 5; i++) j.s[i] = s[i];
    for (int i = 0; i < 4; i++) j.fan[i] = fan[i];
    for (int i = 0; i < 5; i++) j.noff[i] = noff[i];
    j.nb_b = nb_b; j.nb_t = nb_t; j.Rout = Rout; j.Rin = Rin;
    j.rows = Rout * Tj; j.blk0 = blk0;
}

extern "C" void kernel_launch(void* const* d_in, const int* in_sizes, int n_in,
                              void* d_out, int out_size) {
    const int*   nodeids    = (const int*)d_in[0];
    const int*   edgetype   = (const int*)d_in[1];
    const int*   neighbors  = (const int*)d_in[2];
    const int*   rneigh     = (const int*)d_in[3];
    const float* base_embed = (const float*)d_in[4];
    const float* type_embed = (const float*)d_in[5];
    const float* rw_embed   = (const float*)d_in[6];
    const float* reflect    = (const float*)d_in[7];
    const float* agg0_self  = (const float*)d_in[8];
    const float* agg0_neigh = (const float*)d_in[9];
    const float* agg1_self  = (const float*)d_in[10];
    const float* agg1_neigh = (const float*)d_in[11];
    const float* rand_self  = (const float*)d_in[12];
    const float* rand_neighw= (const float*)d_in[13];
    const float* vWq = (const float*)d_in[14];
    const float* vWk = (const float*)d_in[15];
    const float* vWv = (const float*)d_in[16];
    const float* vWf = (const float*)d_in[17];
    const float* vg  = (const float*)d_in[18];
    const float* vb  = (const float*)d_in[19];
    const float* mWq = (const float*)d_in[20];
    const float* mWk = (const float*)d_in[21];
    const float* mWv = (const float*)d_in[22];
    const float* mWf = (const float*)d_in[23];
    const float* mg  = (const float*)d_in[24];
    const float* mb  = (const float*)d_in[25];
    float* outp = (float*)d_out;

    float* buf = nullptr;
    cudaGetSymbolAddress((void**)&buf, g_buf);

    cudaFuncSetAttribute(agg_multi_kernel,
                         cudaFuncAttributeMaxDynamicSharedMemorySize, AGG_SMEM_BYTES);
    cudaFuncSetAttribute(tail_kernel,
                         cudaFuncAttributeMaxDynamicSharedMemorySize, TK_SMEM_BYTES);

    const int s1[5]  = {1, 3, 15, 105, 945};
    const int f1[4]  = {3, 5, 7, 9};
    const int no1[5] = {0, 18, 21, 36, 141};
    const int s1b[5] = {1, 3, 15, 105, 0};
    const int f1b[4] = {3, 5, 7, 0};
    const int s0[5]  = {1, 3, 15, 0, 0};
    const int f0[4]  = {3, 5, 0, 0};
    const int no0[5] = {0, 0, 3, 0, 0};
    const int sT[5]  = {1, 3, 0, 0, 0};
    const int fT[4]  = {3, 0, 0, 0};
    const int noZ[5] = {0, 0, 0, 0, 0};

    MultiParams p;
    p.nodeids = nodeids;

    // ===== launch 1: all level-0 jobs =====
    {
        int b0 = 0;
        set_job(p.job[0], type_embed, buf + SCH1_L0, agg1_self, agg1_neigh, neighbors,
                1, 1, 4, s1, f1, no1, 2 * TOTAL_P, TOTAL_P, BSZ * 124, 0, 2, b0);
        b0 += (p.job[0].rows + 63) / 64;
        set_job(p.job[1], type_embed, buf + SCH0_L0, agg0_self, agg0_neigh, neighbors,
                1, 0, 2, s0, f0, no0, 2 * TOTAL_P, TOTAL_P, BSZ * 4, 0, 2, b0);
        b0 += (p.job[1].rows + 63) / 64;
        set_job(p.job[2], rw_embed, buf + RAND_L0, rand_self, rand_neighw, rneigh,
                2, 0, 2, s0, f0, no0, 18, 0, BSZ * 4, 0, 1, b0);
        b0 += (p.job[2].rows + 63) / 64;
        p.njobs = 3;
        agg_multi_kernel<<<b0, 160, AGG_SMEM_BYTES>>>(p);
    }
    // ===== launch 2: all level-1 jobs =====
    {
        int b0 = 0;
        set_job(p.job[0], buf + SCH1_L0, buf + SCH1_L1, agg1_self + 5000, agg1_neigh + 5000,
                nullptr, 0, 0, 3, s1b, f1b, noZ, 0, 0, BSZ * 19, BSZ * 124, 2, b0);
        b0 += (p.job[0].rows + 63) / 64;
        set_job(p.job[1], buf + SCH0_L0, buf + SPEC0, agg0_self + 5000, agg0_neigh + 5000,
                nullptr, 0, 0, 1, sT, fT, noZ, 0, 0, BSZ, BSZ * 4, 2, b0);
        b0 += (p.job[1].rows + 63) / 64;
        set_job(p.job[2], buf + RAND_L0, buf + RVIEW, rand_self + 5000, rand_neighw + 5000,
                nullptr, 0, 0, 1, sT, fT, noZ, 0, 0, BSZ, BSZ * 4, 1, b0);
        b0 += (p.job[2].rows + 63) / 64;
        p.njobs = 3;
        agg_multi_kernel<<<b0, 160, AGG_SMEM_BYTES>>>(p);
    }

    // ===== launch 3: fused tail =====
    tail_kernel<<<BSZ, NTH, TK_SMEM_BYTES>>>(
        buf + SCH1_L1, buf + SPEC0, buf + RVIEW,
        agg1_self, agg1_neigh,
        edgetype, nodeids, base_embed, reflect,
        vWq, vWk, vWv, vWf, vg, vb,
        mWq, mWk, mWv, mWf, mg, mb,
        outp);
}

// round 11
// speedup vs baseline: 1.2692x; 1.0077x over previous
#include <cuda_runtime.h>
#include <math.h>

// ---------------- problem constants ----------------
#define BSZ 512
#define DD 100
#define TOTAL_P 1086
#define NTH 256

// scratch buffer offsets (floats)
#define SCH1_L0 0ull            // [2][512*124][100]
#define SCH1_L1 12697600ull     // [2][512*19][100]
#define SCH0_L0 14643200ull     // [2][512*4][100]
#define SPEC0   15052800ull     // [2][512][100]
#define RAND_L0 15155200ull     // [512*4][100]
#define RVIEW   15360000ull     // [512][100]
#define SCRATCH_TOTAL 15411200ull

__device__ float g_buf[SCRATCH_TOTAL];

typedef unsigned long long ull;

__device__ __forceinline__ ull fma2(ull a, ull b, ull c) {
    ull d;
    asm("fma.rn.f32x2 %0, %1, %2, %3;" : "=l"(d) : "l"(a), "l"(b), "l"(c));
    return d;
}
__device__ __forceinline__ ull pack2(float a) {
    ull d;
    asm("mov.b64 %0, {%1, %1};" : "=l"(d) : "f"(a));
    return d;
}
__device__ __forceinline__ void unpack2(ull v, float& lo, float& hi) {
    asm("mov.b64 {%0, %1}, %2;" : "=f"(lo), "=f"(hi) : "l"(v));
}

// ================= GEMM-style aggregation kernel (unchanged from R9 best) =================
struct Job {
    const float* gsrc;
    float*       out;
    const float* Ws;
    const float* Wn;
    const int*   neigh;
    int mode;
    int idx;
    int nseg;
    int s[5];
    int fan[4];
    int noff[5];
    int nb_b, nb_t;
    int Rout;
    int Rin;
    int rows;
    int blk0;
};
struct MultiParams {
    Job job[3];
    int njobs;
    const int* nodeids;
};

#define SM_AS   0
#define SM_AM   2320
#define SM_W    4640
#define SM_SELF 8240
#define SM_FAN  8304
#define SM_COFF 8368
#define SM_INVF 8944
#define SM_FLOATS 9008
#define AGG_SMEM_BYTES (SM_FLOATS * 4)

__device__ __forceinline__ void gstep(float a0, float a1, float a2, float a3,
                                      const float* wrow, ull acc[4][5]) {
    ull p0 = pack2(a0), p1 = pack2(a1), p2 = pack2(a2), p3 = pack2(a3);
    const ull* wp = (const ull*)wrow;
    ull w0 = wp[0], w1 = wp[1], w2 = wp[2], w3 = wp[3], w4 = wp[4];
    acc[0][0] = fma2(p0, w0, acc[0][0]); acc[0][1] = fma2(p0, w1, acc[0][1]);
    acc[0][2] = fma2(p0, w2, acc[0][2]); acc[0][3] = fma2(p0, w3, acc[0][3]);
    acc[0][4] = fma2(p0, w4, acc[0][4]);
    acc[1][0] = fma2(p1, w0, acc[1][0]); acc[1][1] = fma2(p1, w1, acc[1][1]);
    acc[1][2] = fma2(p1, w2, acc[1][2]); acc[1][3] = fma2(p1, w3, acc[1][3]);
    acc[1][4] = fma2(p1, w4, acc[1][4]);
    acc[2][0] = fma2(p2, w0, acc[2][0]); acc[2][1] = fma2(p2, w1, acc[2][1]);
    acc[2][2] = fma2(p2, w2, acc[2][2]); acc[2][3] = fma2(p2, w3, acc[2][3]);
    acc[2][4] = fma2(p2, w4, acc[2][4]);
    acc[3][0] = fma2(p3, w0, acc[3][0]); acc[3][1] = fma2(p3, w1, acc[3][1]);
    acc[3][2] = fma2(p3, w2, acc[3][2]); acc[3][3] = fma2(p3, w3, acc[3][3]);
    acc[3][4] = fma2(p3, w4, acc[3][4]);
}

__global__ __launch_bounds__(160, 5) void agg_multi_kernel(MultiParams p) {
    extern __shared__ float sm[];
    float* sAs  = sm + SM_AS;
    float* sAm  = sm + SM_AM;
    float* sW   = sm + SM_W;
    int*   sSelf = (int*)(sm + SM_SELF);
    int*   sFan  = (int*)(sm + SM_FAN);
    int*   sCoff = (int*)(sm + SM_COFF);
    float* sInvF = sm + SM_INVF;

    const int tid = threadIdx.x;

    int j = 0;
    if (p.njobs > 1 && (int)blockIdx.x >= p.job[1].blk0) j = 1;
    if (p.njobs > 2 && (int)blockIdx.x >= p.job[2].blk0) j = 2;
    Job jb = p.job[j];
    const int R0 = (blockIdx.x - jb.blk0) * 64;

    if (tid < 64) {
        int R = R0 + tid;
        if (R >= jb.rows) R = jb.rows - 1;
        int t = (R >= jb.Rout) ? 1 : 0;
        int g = R - t * jb.Rout;
        int kk = 0, off = 0;
        while (kk + 1 < jb.nseg && g >= off + BSZ * jb.s[kk]) { off += BSZ * jb.s[kk]; kk++; }
        int local = g - off;
        int b = local / jb.s[kk];
        int i = local - b * jb.s[kk];
        int fan = jb.fan[kk];
        sFan[tid]  = fan;
        sInvF[tid] = 1.0f / (float)fan;
        int soff;
        if (jb.mode == 0) {
            soff = (t * jb.Rin + g) * DD;
        } else {
            int id = (kk == 0) ? p.nodeids[b]
                               : jb.neigh[b * jb.nb_b + t * jb.nb_t + jb.noff[kk] + i];
            soff = (jb.mode == 1) ? (id * 400 + t * 200 + jb.idx * 100) : id * DD;
        }
        sSelf[tid] = soff;
        if (jb.mode == 0) {
            int off2 = off + BSZ * jb.s[kk];
            int base = (t * jb.Rin + off2 + b * jb.s[kk + 1] + i * fan) * DD;
            for (int jj = 0; jj < fan; jj++) sCoff[tid * 9 + jj] = base + jj * DD;
        } else {
            int nb2 = b * jb.nb_b + t * jb.nb_t + jb.noff[kk + 1] + i * fan;
            for (int jj = 0; jj < fan; jj++) {
                int id = jb.neigh[nb2 + jj];
                sCoff[tid * 9 + jj] = (jb.mode == 1) ? (id * 400 + t * 200 + jb.idx * 100)
                                                     : id * DD;
            }
        }
    }

    const int ct = tid % 10, rt = tid / 10;
    const int c0 = ct * 10;

    ull acc[4][5];
#pragma unroll
    for (int r = 0; r < 4; r++)
#pragma unroll
        for (int q = 0; q < 5; q++) acc[r][q] = 0ull;

    const float* src = jb.gsrc;

#pragma unroll 1
    for (int c = 0; c < 3; c++) {
        const int k0  = (c == 0) ? 0 : (c == 1 ? 36 : 68);
        const int nk  = (c == 0) ? 36 : 32;
        const int nk4 = nk / 4;
        const int nItems = 64 * nk4;

        __syncthreads();

        {
            const float* Ws = jb.Ws;
            const float* Wn = jb.Wn;
            for (int e = tid; e < nk * 50; e += 160) {
                int k = e / 50, cc = (e - k * 50) * 2;
                float2 v;
                if (cc < 50) v = *(const float2*)(Ws + (k0 + k) * 50 + cc);
                else         v = *(const float2*)(Wn + (k0 + k) * 50 + (cc - 50));
                *(float2*)&sW[k * 100 + cc] = v;
            }
        }
#pragma unroll 2
        for (int i = 0; i < 4; i++) {
            int e = tid + i * 160;
            bool ok = e < nItems;
            int row, q;
            if (ok) { row = e / nk4; q = e - row * nk4; }
            else    { row = 0; q = 0; }
            float4 sv = *(const float4*)(src + sSelf[row] + k0 + 4 * q);
            int f = sFan[row];
            const int* co = sCoff + row * 9;
            float x = 0.f, y = 0.f, z = 0.f, w = 0.f;
#pragma unroll
            for (int jj = 0; jj < 9; jj++) {
                if (jj < f) {
                    float4 v = *(const float4*)(src + co[jj] + k0 + 4 * q);
                    x += v.x; y += v.y; z += v.z; w += v.w;
                }
            }
            if (ok) {
                *(float4*)&sAs[row * 36 + 4 * q] = sv;
                float iv = sInvF[row];
                float4 r; r.x = x * iv; r.y = y * iv; r.z = z * iv; r.w = w * iv;
                *(float4*)&sAm[row * 36 + 4 * q] = r;
            }
        }
        __syncthreads();

        const float* Ab = (ct < 5) ? sAs : sAm;
        const float* A0 = Ab + (rt +  0) * 36;
        const float* A1 = Ab + (rt + 16) * 36;
        const float* A2 = Ab + (rt + 32) * 36;
        const float* A3 = Ab + (rt + 48) * 36;

#pragma unroll 2
        for (int k = 0; k < nk; k += 4) {
            float4 a0 = *(const float4*)(A0 + k);
            float4 a1 = *(const float4*)(A1 + k);
            float4 a2 = *(const float4*)(A2 + k);
            float4 a3 = *(const float4*)(A3 + k);
            gstep(a0.x, a1.x, a2.x, a3.x, &sW[(k + 0) * 100 + c0], acc);
            gstep(a0.y, a1.y, a2.y, a3.y, &sW[(k + 1) * 100 + c0], acc);
            gstep(a0.z, a1.z, a2.z, a3.z, &sW[(k + 2) * 100 + c0], acc);
            gstep(a0.w, a1.w, a2.w, a3.w, &sW[(k + 3) * 100 + c0], acc);
        }
    }

#pragma unroll
    for (int r = 0; r < 4; r++) {
        int R = R0 + rt + 16 * r;
        if (R < jb.rows) {
            int t = (R >= jb.Rout) ? 1 : 0;
            int g = R - t * jb.Rout;
            float* op = jb.out + (size_t)(t * jb.Rout + g) * DD + c0;
#pragma unroll
            for (int q = 0; q < 5; q++) {
                float lo, hi;
                unpack2(acc[r][q], lo, hi);
                float2 o;
                o.x = fmaxf(lo, 0.f);
                o.y = fmaxf(hi, 0.f);
                *(float2*)(op + 2 * q) = o;
            }
        }
    }
}

// ================= fused small-tail kernel: sch1 L2+L3 + attention + final =================
#define TK_W    0
#define TK_F1   10000
#define TK_F2   11900
#define TK_M    12300
#define TK_SPEC 12800
#define TK_SCR  13400
#define TK_MISC 16400
#define TK_FLOATS 17000
#define TK_SMEM_BYTES (TK_FLOATS * 4)

__device__ __forceinline__ void load_W(float* W, const float* Ws, const float* Wn, int tid) {
    for (int e = tid; e < 5000; e += NTH) {
        int k = e / 50, c2 = (e - k * 50) * 2;
        float2 v;
        if (c2 < 50) v = *(const float2*)(Ws + k * 50 + c2);
        else         v = *(const float2*)(Wn + k * 50 + (c2 - 50));
        *(float2*)&W[k * 100 + c2] = v;
    }
}

__device__ __forceinline__ void do_level(
    const float* IN, float* OUT, float* M, const float* W,
    int nout, int O1, int O2, int O3, int F0, int F1, int F2, int tid)
{
    for (int it = tid; it < nout * 25; it += NTH) {
        int j = it / 25, k4 = (it - (it / 25) * 25) * 4;
        int k = (j >= O2) ? 2 : ((j >= O1) ? 1 : 0);
        int f  = (k == 0) ? F0 : (k == 1 ? F1 : F2);
        int o  = (k == 0) ? 0  : (k == 1 ? O1 : O2);
        int cs = (k == 0) ? O1 : (k == 1 ? O2 : O3);
        int cb = cs + (j - o) * f;
        float x = 0.f, y = 0.f, z = 0.f, w = 0.f;
        for (int i = 0; i < f; i++) {
            float4 v = *(const float4*)&IN[(cb + i) * 100 + k4];
            x += v.x; y += v.y; z += v.z; w += v.w;
        }
        float iv = 1.0f / (float)f;
        float4 r; r.x = x * iv; r.y = y * iv; r.z = z * iv; r.w = w * iv;
        *(float4*)&M[j * 100 + k4] = r;
    }
    __syncthreads();
    for (int it = tid; it < nout * 50; it += NTH) {
        int j = it / 50, cc = it - (it / 50) * 50;
        int h = cc / 25, c2 = cc - h * 25;
        int col = h * 50 + c2 * 2;
        const float* A = h ? (M + j * 100) : (IN + j * 100);
        ull acc = 0ull;
#pragma unroll 4
        for (int k = 0; k < 100; k++) {
            ull wv = *(const ull*)&W[k * 100 + col];
            acc = fma2(pack2(A[k]), wv, acc);
        }
        float lo, hi; unpack2(acc, lo, hi);
        OUT[j * 100 + col]     = fmaxf(lo, 0.f);
        OUT[j * 100 + col + 1] = fmaxf(hi, 0.f);
    }
    __syncthreads();
}

// attention stage: 6 rows always (nb*na == 6). Split heavy matmuls across
// two warp-aligned thread groups: A = tid<100 (warps 0-3), B = 128<=tid<228.
__device__ __forceinline__ void mha_stage(
    float* X, float* LNX, float* Q, float* K, float* V, float* O,
    float* mu, float* rs, float* SC, float* ATT,
    int nb, int na,
    const float* __restrict__ Wq, const float* __restrict__ Wk,
    const float* __restrict__ Wv, const float* __restrict__ Wf,
    const float* __restrict__ gam, const float* __restrict__ bet, int tid)
{
    const int wd = tid >> 5, ln = tid & 31;
    // layernorm stats: one warp per row, sum + sumsq with shfl reduce
    if (wd < 6) {
        float s = 0.f, sq = 0.f;
        for (int d = ln; d < 100; d += 32) {
            float v = X[wd * 100 + d];
            s += v; sq += v * v;
        }
#pragma unroll
        for (int o2 = 16; o2; o2 >>= 1) {
            s  += __shfl_xor_sync(0xffffffffu, s,  o2);
            sq += __shfl_xor_sync(0xffffffffu, sq, o2);
        }
        if (ln == 0) {
            float m = s * 0.01f;
            mu[wd] = m;
            rs[wd] = rsqrtf(fmaxf(sq * 0.01f - m * m, 0.f) + 1e-6f);
        }
    }
    __syncthreads();
    for (int e = tid; e < 600; e += NTH) {
        int r = e / 100, d = e - r * 100;
        LNX[e] = (X[e] - mu[r]) * rs[r] * gam[d] + bet[d];
    }
    __syncthreads();
    // QKV split: group A -> Q(6 rows) + K rows 0-2 ; group B -> K rows 3-5 + V(6 rows)
    if (tid < 100) {
        float aq[6], ak[3];
#pragma unroll
        for (int r = 0; r < 6; r++) aq[r] = 0.f;
#pragma unroll
        for (int r = 0; r < 3; r++) ak[r] = 0.f;
        for (int k2 = 0; k2 < 100; k2++) {
            float wq = Wq[k2 * 100 + tid];
            float wk = Wk[k2 * 100 + tid];
#pragma unroll
            for (int r = 0; r < 6; r++) aq[r] += LNX[r * 100 + k2] * wq;
#pragma unroll
            for (int r = 0; r < 3; r++) ak[r] += X[r * 100 + k2] * wk;
        }
#pragma unroll
        for (int r = 0; r < 6; r++) Q[r * 100 + tid] = aq[r];
#pragma unroll
        for (int r = 0; r < 3; r++) K[r * 100 + tid] = ak[r];
    } else if (tid >= 128 && tid < 228) {
        const int t2 = tid - 128;
        float ak[3], av[6];
#pragma unroll
        for (int r = 0; r < 3; r++) ak[r] = 0.f;
#pragma unroll
        for (int r = 0; r < 6; r++) av[r] = 0.f;
        for (int k2 = 0; k2 < 100; k2++) {
            float wk = Wk[k2 * 100 + t2];
            float wv = Wv[k2 * 100 + t2];
#pragma unroll
            for (int r = 0; r < 3; r++) ak[r] += X[(r + 3) * 100 + k2] * wk;
#pragma unroll
            for (int r = 0; r < 6; r++) av[r] += X[r * 100 + k2] * wv;
        }
#pragma unroll
        for (int r = 0; r < 3; r++) K[(r + 3) * 100 + t2] = ak[r];
#pragma unroll
        for (int r = 0; r < 6; r++) V[r * 100 + t2] = av[r];
    }
    __syncthreads();
    int nsc = nb * na * na;
    if (tid < nsc) {
        int bi = tid / (na * na), rem = tid - bi * na * na;
        int qa = rem / na, ka = rem - qa * na;
        const float* qp = Q + (bi * na + qa) * 100;
        const float* kp = K + (bi * na + ka) * 100;
        float s = 0.f;
        for (int d = 0; d < 100; d++) s += qp[d] * kp[d];
        SC[tid] = s * 0.1f;
    }
    __syncthreads();
    if (tid < nb * na) {
        int base = tid * na;
        float mx = -1e30f;
        for (int ka = 0; ka < na; ka++) mx = fmaxf(mx, SC[base + ka]);
        float ev[3], sum = 0.f;
        for (int ka = 0; ka < na; ka++) { ev[ka] = expf(SC[base + ka] - mx); sum += ev[ka]; }
        float inv = 1.0f / sum;
        for (int ka = 0; ka < na; ka++) ATT[base + ka] = ev[ka] * inv;
    }
    __syncthreads();
    if (tid < 100) {
        for (int bi = 0; bi < nb; bi++)
            for (int qa = 0; qa < na; qa++) {
                float acc = 0.f;
                for (int ka = 0; ka < na; ka++)
                    acc += ATT[(bi * na + qa) * na + ka] * V[(bi * na + ka) * 100 + tid];
                O[(bi * na + qa) * 100 + tid] = acc;
            }
    }
    __syncthreads();
    // Wf + residual: group A rows 0-2, group B rows 3-5
    if (tid < 100) {
        float acc[3];
#pragma unroll
        for (int r = 0; r < 3; r++) acc[r] = 0.f;
        for (int k2 = 0; k2 < 100; k2++) {
            float wf = Wf[k2 * 100 + tid];
#pragma unroll
            for (int r = 0; r < 3; r++) acc[r] += O[r * 100 + k2] * wf;
        }
#pragma unroll
        for (int r = 0; r < 3; r++) X[r * 100 + tid] = acc[r] + X[r * 100 + tid];
    } else if (tid >= 128 && tid < 228) {
        const int t2 = tid - 128;
        float acc[3];
#pragma unroll
        for (int r = 0; r < 3; r++) acc[r] = 0.f;
        for (int k2 = 0; k2 < 100; k2++) {
            float wf = Wf[k2 * 100 + t2];
#pragma unroll
            for (int r = 0; r < 3; r++) acc[r] += O[(r + 3) * 100 + k2] * wf;
        }
#pragma unroll
        for (int r = 0; r < 3; r++) X[(r + 3) * 100 + t2] = acc[r] + X[(r + 3) * 100 + t2];
    }
    __syncthreads();
}

__global__ __launch_bounds__(NTH) void tail_kernel(
    const float* __restrict__ sch1_l1,
    const float* __restrict__ spec0g, const float* __restrict__ rviewg,
    const float* __restrict__ agg1_self, const float* __restrict__ agg1_neigh,
    const int* __restrict__ edgetype, const int* __restrict__ nodeids,
    const float* __restrict__ base_embed, const float* __restrict__ reflect,
    const float* __restrict__ vWq, const float* __restrict__ vWk,
    const float* __restrict__ vWv, const float* __restrict__ vWf,
    const float* __restrict__ vg, const float* __restrict__ vb,
    const float* __restrict__ mWq, const float* __restrict__ mWk,
    const float* __restrict__ mWv, const float* __restrict__ mWf,
    const float* __restrict__ mg, const float* __restrict__ mb,
    float* __restrict__ outp)
{
    extern __shared__ float sm[];
    float* W    = sm + TK_W;
    float* F1   = sm + TK_F1;
    float* F2   = sm + TK_F2;
    float* M    = sm + TK_M;
    float* SPEC = sm + TK_SPEC;
    float* SCR  = sm + TK_SCR;
    float* MISC = sm + TK_MISC;

    const int b = blockIdx.x;
    const int tid = threadIdx.x;

    for (int t = 0; t < 2; t++) {
        const float* L1 = sch1_l1 + (size_t)t * (512 * 19) * 100;
        for (int e = tid; e < 19 * 25; e += NTH) {
            int row = e / 25, k4 = (e - (e / 25) * 25) * 4;
            int g;
            if (row == 0)      g = b;
            else if (row < 4)  g = 512 + b * 3 + (row - 1);
            else               g = 2048 + b * 15 + (row - 4);
            *(float4*)&F1[row * 100 + k4] = *(const float4*)&L1[(size_t)g * 100 + k4];
        }
        load_W(W, agg1_self + 10000, agg1_neigh + 10000, tid);
        __syncthreads();
        do_level(F1, F2, M, W, 4, 1, 4, 19, 3, 5, 0, tid);
        load_W(W, agg1_self + 15000, agg1_neigh + 15000, tid);
        __syncthreads();
        do_level(F2, SPEC + (2 + t) * 100, M, W, 1, 1, 999, 999, 3, 0, 0, tid);
    }
    for (int e = tid; e < 200; e += NTH) {
        int t = e / 100, d = e - t * 100;
        SPEC[t * 100 + d] = spec0g[(size_t)(t * BSZ + b) * 100 + d];
    }
    for (int e = tid; e < 100; e += NTH) {
        float v = rviewg[(size_t)b * 100 + e];
        SPEC[4 * 100 + e] = v;
        SPEC[5 * 100 + e] = v;
    }
    __syncthreads();

    float* X   = SPEC;
    float* LNX = SCR;
    float* Q   = SCR + 600;
    float* K   = SCR + 1200;
    float* V   = SCR + 1800;
    float* O   = SCR + 2400;
    float* TMP = F1;
    float* mu  = MISC;
    float* rs  = MISC + 8;
    float* SC  = MISC + 16;
    float* ATT = MISC + 48;
    float* SEL = MISC + 80;
    float* RES = MISC + 192;
    float* part = MISC + 400;

    mha_stage(X, LNX, Q, K, V, O, mu, rs, SC, ATT, 3, 2, vWq, vWk, vWv, vWf, vg, vb, tid);

    for (int e = tid; e < 600; e += NTH) TMP[e] = X[e];
    __syncthreads();
    for (int e = tid; e < 600; e += NTH) {
        int r = e / 100, d = e - r * 100;
        int t = r / 3, v = r - t * 3;
        X[e] = TMP[(v * 2 + t) * 100 + d];
    }
    __syncthreads();

    mha_stage(X, LNX, Q, K, V, O, mu, rs, SC, ATT, 2, 3, mWq, mWk, mWv, mWf, mg, mb, tid);

    const int typ = edgetype[BSZ + b];
    if (tid < 100) {
        SEL[tid] = (X[(typ * 3 + 0) * 100 + tid] +
                    X[(typ * 3 + 1) * 100 + tid] +
                    X[(typ * 3 + 2) * 100 + tid]) * (1.0f / 3.0f);
    }
    __syncthreads();

    const int node = nodeids[b];
    for (int o = tid; o < 200; o += NTH) {
        float acc = 0.f;
        const float* rp = reflect + (size_t)typ * 100 * 200 + o;
        for (int d = 0; d < 100; d++) acc += SEL[d] * rp[d * 200];
        RES[o] = base_embed[(size_t)node * 200 + o] + acc;
    }
    __syncthreads();
    float ps = 0.f;
    for (int o = tid; o < 200; o += NTH) ps += RES[o] * RES[o];
#pragma unroll
    for (int o2 = 16; o2; o2 >>= 1) ps += __shfl_xor_sync(0xffffffffu, ps, o2);
    if ((tid & 31) == 0) part[tid >> 5] = ps;
    __syncthreads();
    if (tid == 0) {
        float s = 0.f;
        for (int i = 0; i < 8; i++) s += part[i];
        part[0] = 1.0f / fmaxf(sqrtf(s), 1e-12f);
    }
    __syncthreads();
    float inv = part[0];
    for (int o = tid; o < 200; o += NTH) outp[(size_t)b * 200 + o] = RES[o] * inv;
}

// ---------------- host launcher ----------------
static void set_job(Job& j, const float* gsrc, float* out, const float* Ws, const float* Wn,
                    const int* neigh, int mode, int idx, int nseg,
                    const int* s, const int* fan, const int* noff,
                    int nb_b, int nb_t, int Rout, int Rin, int Tj, int blk0) {
    j.gsrc = gsrc; j.out = out; j.Ws = Ws; j.Wn = Wn; j.neigh = neigh;
    j.mode = mode; j.idx = idx; j.nseg = nseg;
    for (int i = 0; i < 5; i++) j.s[i] = s[i];
    for (int i = 0; i < 4; i++) j.fan[i] = fan[i];
    for (int i = 0; i < 5; i++) j.noff[i] = noff[i];
    j.nb_b = nb_b; j.nb_t = nb_t; j.Rout = Rout; j.Rin = Rin;
    j.rows = Rout * Tj; j.blk0 = blk0;
}

extern "C" void kernel_launch(void* const* d_in, const int* in_sizes, int n_in,
                              void* d_out, int out_size) {
    const int*   nodeids    = (const int*)d_in[0];
    const int*   edgetype   = (const int*)d_in[1];
    const int*   neighbors  = (const int*)d_in[2];
    const int*   rneigh     = (const int*)d_in[3];
    const float* base_embed = (const float*)d_in[4];
    const float* type_embed = (const float*)d_in[5];
    const float* rw_embed   = (const float*)d_in[6];
    const float* reflect    = (const float*)d_in[7];
    const float* agg0_self  = (const float*)d_in[8];
    const float* agg0_neigh = (const float*)d_in[9];
    const float* agg1_self  = (const float*)d_in[10];
    const float* agg1_neigh = (const float*)d_in[11];
    const float* rand_self  = (const float*)d_in[12];
    const float* rand_neighw= (const float*)d_in[13];
    const float* vWq = (const float*)d_in[14];
    const float* vWk = (const float*)d_in[15];
    const float* vWv = (const float*)d_in[16];
    const float* vWf = (const float*)d_in[17];
    const float* vg  = (const float*)d_in[18];
    const float* vb  = (const float*)d_in[19];
    const float* mWq = (const float*)d_in[20];
    const float* mWk = (const float*)d_in[21];
    const float* mWv = (const float*)d_in[22];
    const float* mWf = (const float*)d_in[23];
    const float* mg  = (const float*)d_in[24];
    const float* mb  = (const float*)d_in[25];
    float* outp = (float*)d_out;

    float* buf = nullptr;
    cudaGetSymbolAddress((void**)&buf, g_buf);

    cudaFuncSetAttribute(agg_multi_kernel,
                         cudaFuncAttributeMaxDynamicSharedMemorySize, AGG_SMEM_BYTES);
    cudaFuncSetAttribute(tail_kernel,
                         cudaFuncAttributeMaxDynamicSharedMemorySize, TK_SMEM_BYTES);

    const int s1[5]  = {1, 3, 15, 105, 945};
    const int f1[4]  = {3, 5, 7, 9};
    const int no1[5] = {0, 18, 21, 36, 141};
    const int s1b[5] = {1, 3, 15, 105, 0};
    const int f1b[4] = {3, 5, 7, 0};
    const int s0[5]  = {1, 3, 15, 0, 0};
    const int f0[4]  = {3, 5, 0, 0};
    const int no0[5] = {0, 0, 3, 0, 0};
    const int sT[5]  = {1, 3, 0, 0, 0};
    const int fT[4]  = {3, 0, 0, 0};
    const int noZ[5] = {0, 0, 0, 0, 0};

    MultiParams p;
    p.nodeids = nodeids;

    // ===== launch 1: all level-0 jobs =====
    {
        int b0 = 0;
        set_job(p.job[0], type_embed, buf + SCH1_L0, agg1_self, agg1_neigh, neighbors,
                1, 1, 4, s1, f1, no1, 2 * TOTAL_P, TOTAL_P, BSZ * 124, 0, 2, b0);
        b0 += (p.job[0].rows + 63) / 64;
        set_job(p.job[1], type_embed, buf + SCH0_L0, agg0_self, agg0_neigh, neighbors,
                1, 0, 2, s0, f0, no0, 2 * TOTAL_P, TOTAL_P, BSZ * 4, 0, 2, b0);
        b0 += (p.job[1].rows + 63) / 64;
        set_job(p.job[2], rw_embed, buf + RAND_L0, rand_self, rand_neighw, rneigh,
                2, 0, 2, s0, f0, no0, 18, 0, BSZ * 4, 0, 1, b0);
        b0 += (p.job[2].rows + 63) / 64;
        p.njobs = 3;
        agg_multi_kernel<<<b0, 160, AGG_SMEM_BYTES>>>(p);
    }
    // ===== launch 2: all level-1 jobs =====
    {
        int b0 = 0;
        set_job(p.job[0], buf + SCH1_L0, buf + SCH1_L1, agg1_self + 5000, agg1_neigh + 5000,
                nullptr, 0, 0, 3, s1b, f1b, noZ, 0, 0, BSZ * 19, BSZ * 124, 2, b0);
        b0 += (p.job[0].rows + 63) / 64;
        set_job(p.job[1], buf + SCH0_L0, buf + SPEC0, agg0_self + 5000, agg0_neigh + 5000,
                nullptr, 0, 0, 1, sT, fT, noZ, 0, 0, BSZ, BSZ * 4, 2, b0);
        b0 += (p.job[1].rows + 63) / 64;
        set_job(p.job[2], buf + RAND_L0, buf + RVIEW, rand_self + 5000, rand_neighw + 5000,
                nullptr, 0, 0, 1, sT, fT, noZ, 0, 0, BSZ, BSZ * 4, 1, b0);
        b0 += (p.job[2].rows + 63) / 64;
        p.njobs = 3;
        agg_multi_kernel<<<b0, 160, AGG_SMEM_BYTES>>>(p);
    }

    // ===== launch 3: fused tail =====
    tail_kernel<<<BSZ, NTH, TK_SMEM_BYTES>>>(
        buf + SCH1_L1, buf + SPEC0, buf + RVIEW,
        agg1_self, agg1_neigh,
        edgetype, nodeids, base_embed, reflect,
        vWq, vWk, vWv, vWf, vg, vb,
        mWq, mWk, mWv, mWf, mg, mb,
        outp);
}

// round 12
// speedup vs baseline: 1.2867x; 1.0138x over previous
#include <cuda_runtime.h>
#include <math.h>

// ---------------- problem constants ----------------
#define BSZ 512
#define DD 100
#define TOTAL_P 1086
#define NTH 256

// scratch buffer offsets (floats)
#define SCH1_L0 0ull            // [2][512*124][100]
#define SCH1_L1 12697600ull     // [2][512*19][100]
#define SCH0_L0 14643200ull     // [2][512*4][100]
#define SPEC0   15052800ull     // [2][512][100]
#define RAND_L0 15155200ull     // [512*4][100]
#define RVIEW   15360000ull     // [512][100]
#define SCRATCH_TOTAL 15411200ull

__device__ float g_buf[SCRATCH_TOTAL];

typedef unsigned long long ull;

__device__ __forceinline__ ull fma2(ull a, ull b, ull c) {
    ull d;
    asm("fma.rn.f32x2 %0, %1, %2, %3;" : "=l"(d) : "l"(a), "l"(b), "l"(c));
    return d;
}
__device__ __forceinline__ ull pack2(float a) {
    ull d;
    asm("mov.b64 %0, {%1, %1};" : "=l"(d) : "f"(a));
    return d;
}
__device__ __forceinline__ void unpack2(ull v, float& lo, float& hi) {
    asm("mov.b64 {%0, %1}, %2;" : "=f"(lo), "=f"(hi) : "l"(v));
}

// ================= GEMM-style aggregation kernel (unchanged R9/R10 best) =================
struct Job {
    const float* gsrc;
    float*       out;
    const float* Ws;
    const float* Wn;
    const int*   neigh;
    int mode;
    int idx;
    int nseg;
    int s[5];
    int fan[4];
    int noff[5];
    int nb_b, nb_t;
    int Rout;
    int Rin;
    int rows;
    int blk0;
};
struct MultiParams {
    Job job[3];
    int njobs;
    const int* nodeids;
};

#define SM_AS   0
#define SM_AM   2320
#define SM_W    4640
#define SM_SELF 8240
#define SM_FAN  8304
#define SM_COFF 8368
#define SM_INVF 8944
#define SM_FLOATS 9008
#define AGG_SMEM_BYTES (SM_FLOATS * 4)

__device__ __forceinline__ void gstep(float a0, float a1, float a2, float a3,
                                      const float* wrow, ull acc[4][5]) {
    ull p0 = pack2(a0), p1 = pack2(a1), p2 = pack2(a2), p3 = pack2(a3);
    const ull* wp = (const ull*)wrow;
    ull w0 = wp[0], w1 = wp[1], w2 = wp[2], w3 = wp[3], w4 = wp[4];
    acc[0][0] = fma2(p0, w0, acc[0][0]); acc[0][1] = fma2(p0, w1, acc[0][1]);
    acc[0][2] = fma2(p0, w2, acc[0][2]); acc[0][3] = fma2(p0, w3, acc[0][3]);
    acc[0][4] = fma2(p0, w4, acc[0][4]);
    acc[1][0] = fma2(p1, w0, acc[1][0]); acc[1][1] = fma2(p1, w1, acc[1][1]);
    acc[1][2] = fma2(p1, w2, acc[1][2]); acc[1][3] = fma2(p1, w3, acc[1][3]);
    acc[1][4] = fma2(p1, w4, acc[1][4]);
    acc[2][0] = fma2(p2, w0, acc[2][0]); acc[2][1] = fma2(p2, w1, acc[2][1]);
    acc[2][2] = fma2(p2, w2, acc[2][2]); acc[2][3] = fma2(p2, w3, acc[2][3]);
    acc[2][4] = fma2(p2, w4, acc[2][4]);
    acc[3][0] = fma2(p3, w0, acc[3][0]); acc[3][1] = fma2(p3, w1, acc[3][1]);
    acc[3][2] = fma2(p3, w2, acc[3][2]); acc[3][3] = fma2(p3, w3, acc[3][3]);
    acc[3][4] = fma2(p3, w4, acc[3][4]);
}

__global__ __launch_bounds__(160, 5) void agg_multi_kernel(MultiParams p) {
    extern __shared__ float sm[];
    float* sAs  = sm + SM_AS;
    float* sAm  = sm + SM_AM;
    float* sW   = sm + SM_W;
    int*   sSelf = (int*)(sm + SM_SELF);
    int*   sFan  = (int*)(sm + SM_FAN);
    int*   sCoff = (int*)(sm + SM_COFF);
    float* sInvF = sm + SM_INVF;

    const int tid = threadIdx.x;

    int j = 0;
    if (p.njobs > 1 && (int)blockIdx.x >= p.job[1].blk0) j = 1;
    if (p.njobs > 2 && (int)blockIdx.x >= p.job[2].blk0) j = 2;
    Job jb = p.job[j];
    const int R0 = (blockIdx.x - jb.blk0) * 64;

    if (tid < 64) {
        int R = R0 + tid;
        if (R >= jb.rows) R = jb.rows - 1;
        int t = (R >= jb.Rout) ? 1 : 0;
        int g = R - t * jb.Rout;
        int kk = 0, off = 0;
        while (kk + 1 < jb.nseg && g >= off + BSZ * jb.s[kk]) { off += BSZ * jb.s[kk]; kk++; }
        int local = g - off;
        int b = local / jb.s[kk];
        int i = local - b * jb.s[kk];
        int fan = jb.fan[kk];
        sFan[tid]  = fan;
        sInvF[tid] = 1.0f / (float)fan;
        int soff;
        if (jb.mode == 0) {
            soff = (t * jb.Rin + g) * DD;
        } else {
            int id = (kk == 0) ? p.nodeids[b]
                               : jb.neigh[b * jb.nb_b + t * jb.nb_t + jb.noff[kk] + i];
            soff = (jb.mode == 1) ? (id * 400 + t * 200 + jb.idx * 100) : id * DD;
        }
        sSelf[tid] = soff;
        if (jb.mode == 0) {
            int off2 = off + BSZ * jb.s[kk];
            int base = (t * jb.Rin + off2 + b * jb.s[kk + 1] + i * fan) * DD;
            for (int jj = 0; jj < fan; jj++) sCoff[tid * 9 + jj] = base + jj * DD;
        } else {
            int nb2 = b * jb.nb_b + t * jb.nb_t + jb.noff[kk + 1] + i * fan;
            for (int jj = 0; jj < fan; jj++) {
                int id = jb.neigh[nb2 + jj];
                sCoff[tid * 9 + jj] = (jb.mode == 1) ? (id * 400 + t * 200 + jb.idx * 100)
                                                     : id * DD;
            }
        }
    }

    const int ct = tid % 10, rt = tid / 10;
    const int c0 = ct * 10;

    ull acc[4][5];
#pragma unroll
    for (int r = 0; r < 4; r++)
#pragma unroll
        for (int q = 0; q < 5; q++) acc[r][q] = 0ull;

    const float* src = jb.gsrc;

#pragma unroll 1
    for (int c = 0; c < 3; c++) {
        const int k0  = (c == 0) ? 0 : (c == 1 ? 36 : 68);
        const int nk  = (c == 0) ? 36 : 32;
        const int nk4 = nk / 4;
        const int nItems = 64 * nk4;

        __syncthreads();

        {
            const float* Ws = jb.Ws;
            const float* Wn = jb.Wn;
            for (int e = tid; e < nk * 50; e += 160) {
                int k = e / 50, cc = (e - k * 50) * 2;
                float2 v;
                if (cc < 50) v = *(const float2*)(Ws + (k0 + k) * 50 + cc);
                else         v = *(const float2*)(Wn + (k0 + k) * 50 + (cc - 50));
                *(float2*)&sW[k * 100 + cc] = v;
            }
        }
#pragma unroll 2
        for (int i = 0; i < 4; i++) {
            int e = tid + i * 160;
            bool ok = e < nItems;
            int row, q;
            if (ok) { row = e / nk4; q = e - row * nk4; }
            else    { row = 0; q = 0; }
            float4 sv = *(const float4*)(src + sSelf[row] + k0 + 4 * q);
            int f = sFan[row];
            const int* co = sCoff + row * 9;
            float x = 0.f, y = 0.f, z = 0.f, w = 0.f;
#pragma unroll
            for (int jj = 0; jj < 9; jj++) {
                if (jj < f) {
                    float4 v = *(const float4*)(src + co[jj] + k0 + 4 * q);
                    x += v.x; y += v.y; z += v.z; w += v.w;
                }
            }
            if (ok) {
                *(float4*)&sAs[row * 36 + 4 * q] = sv;
                float iv = sInvF[row];
                float4 r; r.x = x * iv; r.y = y * iv; r.z = z * iv; r.w = w * iv;
                *(float4*)&sAm[row * 36 + 4 * q] = r;
            }
        }
        __syncthreads();

        const float* Ab = (ct < 5) ? sAs : sAm;
        const float* A0 = Ab + (rt +  0) * 36;
        const float* A1 = Ab + (rt + 16) * 36;
        const float* A2 = Ab + (rt + 32) * 36;
        const float* A3 = Ab + (rt + 48) * 36;

#pragma unroll 2
        for (int k = 0; k < nk; k += 4) {
            float4 a0 = *(const float4*)(A0 + k);
            float4 a1 = *(const float4*)(A1 + k);
            float4 a2 = *(const float4*)(A2 + k);
            float4 a3 = *(const float4*)(A3 + k);
            gstep(a0.x, a1.x, a2.x, a3.x, &sW[(k + 0) * 100 + c0], acc);
            gstep(a0.y, a1.y, a2.y, a3.y, &sW[(k + 1) * 100 + c0], acc);
            gstep(a0.z, a1.z, a2.z, a3.z, &sW[(k + 2) * 100 + c0], acc);
            gstep(a0.w, a1.w, a2.w, a3.w, &sW[(k + 3) * 100 + c0], acc);
        }
    }

#pragma unroll
    for (int r = 0; r < 4; r++) {
        int R = R0 + rt + 16 * r;
        if (R < jb.rows) {
            int t = (R >= jb.Rout) ? 1 : 0;
            int g = R - t * jb.Rout;
            float* op = jb.out + (size_t)(t * jb.Rout + g) * DD + c0;
#pragma unroll
            for (int q = 0; q < 5; q++) {
                float lo, hi;
                unpack2(acc[r][q], lo, hi);
                float2 o;
                o.x = fmaxf(lo, 0.f);
                o.y = fmaxf(hi, 0.f);
                *(float2*)(op + 2 * q) = o;
            }
        }
    }
}

// ================= fused small-tail kernel (rewritten) =================
// smem (floats): F1[3800] F2[800] M[800] SPEC[600] SCR[3000] MISC[600] = 9600 -> 38.4KB
#define TK_F1   0
#define TK_F2   3800
#define TK_M    4600
#define TK_SPEC 5400
#define TK_SCR  6000
#define TK_MISC 9000
#define TK_FLOATS 9600
#define TK_SMEM_BYTES (TK_FLOATS * 4)

// dot product of smem row A (100) against global weight half (Ws or Wn) column
// pair wcol; dual accumulator chains over even/odd k.
__device__ __forceinline__ void dot_w(const float* A, const float* Wh, int wcol,
                                      float& lo, float& hi) {
    ull a0 = 0ull, a1 = 0ull;
#pragma unroll 4
    for (int k = 0; k < 100; k += 2) {
        ull w0 = __ldg((const ull*)(Wh + k * 50 + wcol));
        ull w1 = __ldg((const ull*)(Wh + (k + 1) * 50 + wcol));
        a0 = fma2(pack2(A[k]), w0, a0);
        a1 = fma2(pack2(A[k + 1]), w1, a1);
    }
    float l0, h0, l1, h1;
    unpack2(a0, l0, h0);
    unpack2(a1, l1, h1);
    lo = l0 + l1;
    hi = h0 + h1;
}

// attention stage (R10 version): heavy matmuls split across two warp groups
__device__ __forceinline__ void mha_stage(
    float* X, float* LNX, float* Q, float* K, float* V, float* O,
    float* mu, float* rs, float* SC, float* ATT,
    int nb, int na,
    const float* __restrict__ Wq, const float* __restrict__ Wk,
    const float* __restrict__ Wv, const float* __restrict__ Wf,
    const float* __restrict__ gam, const float* __restrict__ bet, int tid)
{
    const int wd = tid >> 5, ln = tid & 31;
    if (wd < 6) {
        float s = 0.f, sq = 0.f;
        for (int d = ln; d < 100; d += 32) {
            float v = X[wd * 100 + d];
            s += v; sq += v * v;
        }
#pragma unroll
        for (int o2 = 16; o2; o2 >>= 1) {
            s  += __shfl_xor_sync(0xffffffffu, s,  o2);
            sq += __shfl_xor_sync(0xffffffffu, sq, o2);
        }
        if (ln == 0) {
            float m = s * 0.01f;
            mu[wd] = m;
            rs[wd] = rsqrtf(fmaxf(sq * 0.01f - m * m, 0.f) + 1e-6f);
        }
    }
    __syncthreads();
    for (int e = tid; e < 600; e += NTH) {
        int r = e / 100, d = e - r * 100;
        LNX[e] = (X[e] - mu[r]) * rs[r] * gam[d] + bet[d];
    }
    __syncthreads();
    if (tid < 100) {
        float aq[6], ak[3];
#pragma unroll
        for (int r = 0; r < 6; r++) aq[r] = 0.f;
#pragma unroll
        for (int r = 0; r < 3; r++) ak[r] = 0.f;
        for (int k2 = 0; k2 < 100; k2++) {
            float wq = __ldg(Wq + k2 * 100 + tid);
            float wk = __ldg(Wk + k2 * 100 + tid);
#pragma unroll
            for (int r = 0; r < 6; r++) aq[r] += LNX[r * 100 + k2] * wq;
#pragma unroll
            for (int r = 0; r < 3; r++) ak[r] += X[r * 100 + k2] * wk;
        }
#pragma unroll
        for (int r = 0; r < 6; r++) Q[r * 100 + tid] = aq[r];
#pragma unroll
        for (int r = 0; r < 3; r++) K[r * 100 + tid] = ak[r];
    } else if (tid >= 128 && tid < 228) {
        const int t2 = tid - 128;
        float ak[3], av[6];
#pragma unroll
        for (int r = 0; r < 3; r++) ak[r] = 0.f;
#pragma unroll
        for (int r = 0; r < 6; r++) av[r] = 0.f;
        for (int k2 = 0; k2 < 100; k2++) {
            float wk = __ldg(Wk + k2 * 100 + t2);
            float wv = __ldg(Wv + k2 * 100 + t2);
#pragma unroll
            for (int r = 0; r < 3; r++) ak[r] += X[(r + 3) * 100 + k2] * wk;
#pragma unroll
            for (int r = 0; r < 6; r++) av[r] += X[r * 100 + k2] * wv;
        }
#pragma unroll
        for (int r = 0; r < 3; r++) K[(r + 3) * 100 + t2] = ak[r];
#pragma unroll
        for (int r = 0; r < 6; r++) V[r * 100 + t2] = av[r];
    }
    __syncthreads();
    int nsc = nb * na * na;
    if (tid < nsc) {
        int bi = tid / (na * na), rem = tid - bi * na * na;
        int qa = rem / na, ka = rem - qa * na;
        const float* qp = Q + (bi * na + qa) * 100;
        const float* kp = K + (bi * na + ka) * 100;
        float s = 0.f;
        for (int d = 0; d < 100; d++) s += qp[d] * kp[d];
        SC[tid] = s * 0.1f;
    }
    __syncthreads();
    if (tid < nb * na) {
        int base = tid * na;
        float mx = -1e30f;
        for (int ka = 0; ka < na; ka++) mx = fmaxf(mx, SC[base + ka]);
        float ev[3], sum = 0.f;
        for (int ka = 0; ka < na; ka++) { ev[ka] = expf(SC[base + ka] - mx); sum += ev[ka]; }
        float inv = 1.0f / sum;
        for (int ka = 0; ka < na; ka++) ATT[base + ka] = ev[ka] * inv;
    }
    __syncthreads();
    if (tid < 100) {
        for (int bi = 0; bi < nb; bi++)
            for (int qa = 0; qa < na; qa++) {
                float acc = 0.f;
                for (int ka = 0; ka < na; ka++)
                    acc += ATT[(bi * na + qa) * na + ka] * V[(bi * na + ka) * 100 + tid];
                O[(bi * na + qa) * 100 + tid] = acc;
            }
    }
    __syncthreads();
    if (tid < 100) {
        float acc[3];
#pragma unroll
        for (int r = 0; r < 3; r++) acc[r] = 0.f;
        for (int k2 = 0; k2 < 100; k2++) {
            float wf = __ldg(Wf + k2 * 100 + tid);
#pragma unroll
            for (int r = 0; r < 3; r++) acc[r] += O[r * 100 + k2] * wf;
        }
#pragma unroll
        for (int r = 0; r < 3; r++) X[r * 100 + tid] = acc[r] + X[r * 100 + tid];
    } else if (tid >= 128 && tid < 228) {
        const int t2 = tid - 128;
        float acc[3];
#pragma unroll
        for (int r = 0; r < 3; r++) acc[r] = 0.f;
        for (int k2 = 0; k2 < 100; k2++) {
            float wf = __ldg(Wf + k2 * 100 + t2);
#pragma unroll
            for (int r = 0; r < 3; r++) acc[r] += O[(r + 3) * 100 + k2] * wf;
        }
#pragma unroll
        for (int r = 0; r < 3; r++) X[(r + 3) * 100 + t2] = acc[r] + X[(r + 3) * 100 + t2];
    }
    __syncthreads();
}

__global__ __launch_bounds__(NTH) void tail_kernel(
    const float* __restrict__ sch1_l1,
    const float* __restrict__ spec0g, const float* __restrict__ rviewg,
    const float* __restrict__ agg1_self, const float* __restrict__ agg1_neigh,
    const int* __restrict__ edgetype, const int* __restrict__ nodeids,
    const float* __restrict__ base_embed, const float* __restrict__ reflect,
    const float* __restrict__ vWq, const float* __restrict__ vWk,
    const float* __restrict__ vWv, const float* __restrict__ vWf,
    const float* __restrict__ vg, const float* __restrict__ vb,
    const float* __restrict__ mWq, const float* __restrict__ mWk,
    const float* __restrict__ mWv, const float* __restrict__ mWf,
    const float* __restrict__ mg, const float* __restrict__ mb,
    float* __restrict__ outp)
{
    extern __shared__ float sm[];
    float* F1   = sm + TK_F1;     // 38 rows: t*19 + row
    float* F2   = sm + TK_F2;     // 8 rows: t*4 + j
    float* M    = sm + TK_M;      // mean scratch (8 rows)
    float* SPEC = sm + TK_SPEC;
    float* SCR  = sm + TK_SCR;
    float* MISC = sm + TK_MISC;

    const int b = blockIdx.x;
    const int tid = threadIdx.x;

    // ---- load schema1 L1 rows for both t (38 rows x 100) ----
    for (int e = tid; e < 38 * 25; e += NTH) {
        int row38 = e / 25, k4 = (e - row38 * 25) * 4;
        int t = (row38 >= 19) ? 1 : 0;
        int row = row38 - t * 19;
        int g;
        if (row == 0)      g = b;
        else if (row < 4)  g = 512 + b * 3 + (row - 1);
        else               g = 2048 + b * 15 + (row - 4);
        *(float4*)&F1[row38 * 100 + k4] =
            *(const float4*)&sch1_l1[((size_t)t * (512 * 19) + g) * 100 + k4];
    }
    __syncthreads();

    // ---- L2 merged (both t): 38 rows -> 8 rows ----
    // mean: 8 rows x 25 k4 = 200 items
    if (tid < 200) {
        int j = tid / 25, k4 = (tid - (tid / 25) * 25) * 4;
        int tb = j >> 2, jj = j & 3;
        int base = tb * 19;
        int f  = (jj == 0) ? 3 : 5;
        int cb = (jj == 0) ? (base + 1) : (base + 4 + (jj - 1) * 5);
        float x = 0.f, y = 0.f, z = 0.f, w = 0.f;
        for (int i = 0; i < f; i++) {
            float4 v = *(const float4*)&F1[(cb + i) * 100 + k4];
            x += v.x; y += v.y; z += v.z; w += v.w;
        }
        float iv = 1.0f / (float)f;
        float4 r; r.x = x * iv; r.y = y * iv; r.z = z * iv; r.w = w * iv;
        *(float4*)&M[j * 100 + k4] = r;
    }
    __syncthreads();
    // GEMM: 8 rows x 50 col-pairs = 400 items
    {
        const float* WsL2 = agg1_self + 10000;
        const float* WnL2 = agg1_neigh + 10000;
        for (int it = tid; it < 400; it += NTH) {
            int j = it / 50, cc = it - (it / 50) * 50;
            int col = cc * 2;
            int h = (col >= 50);
            int wcol = col - h * 50;
            int tb = j >> 2, jj = j & 3;
            const float* A = h ? (M + j * 100) : (F1 + (tb * 19 + jj) * 100);
            const float* Wh = h ? WnL2 : WsL2;
            float lo, hi;
            dot_w(A, Wh, wcol, lo, hi);
            F2[j * 100 + col]     = fmaxf(lo, 0.f);
            F2[j * 100 + col + 1] = fmaxf(hi, 0.f);
        }
    }
    __syncthreads();

    // ---- L3 merged (both t): 8 rows -> 2 spec rows ----
    if (tid < 50) {
        int j = tid / 25, k4 = (tid - (tid / 25) * 25) * 4;
        int base = j * 4;
        float x = 0.f, y = 0.f, z = 0.f, w = 0.f;
        for (int i = 1; i <= 3; i++) {
            float4 v = *(const float4*)&F2[(base + i) * 100 + k4];
            x += v.x; y += v.y; z += v.z; w += v.w;
        }
        const float iv = 1.0f / 3.0f;
        float4 r; r.x = x * iv; r.y = y * iv; r.z = z * iv; r.w = w * iv;
        *(float4*)&M[j * 100 + k4] = r;
    }
    __syncthreads();
    {
        const float* WsL3 = agg1_self + 15000;
        const float* WnL3 = agg1_neigh + 15000;
        if (tid < 100) {
            int j = tid / 50, cc = tid - (tid / 50) * 50;
            int col = cc * 2;
            int h = (col >= 50);
            int wcol = col - h * 50;
            const float* A = h ? (M + j * 100) : (F2 + (j * 4) * 100);
            const float* Wh = h ? WnL3 : WsL3;
            float lo, hi;
            dot_w(A, Wh, wcol, lo, hi);
            SPEC[(2 + j) * 100 + col]     = fmaxf(lo, 0.f);
            SPEC[(2 + j) * 100 + col + 1] = fmaxf(hi, 0.f);
        }
    }
    // spec0 (v=0) and rview (v=2)
    for (int e = tid; e < 200; e += NTH) {
        int t = e / 100, d = e - t * 100;
        SPEC[t * 100 + d] = spec0g[(size_t)(t * BSZ + b) * 100 + d];
    }
    for (int e = tid; e < 100; e += NTH) {
        float v = rviewg[(size_t)b * 100 + e];
        SPEC[4 * 100 + e] = v;
        SPEC[5 * 100 + e] = v;
    }
    __syncthreads();

    // ---- attention + final ----
    float* X   = SPEC;          // rows v*2+t
    float* LNX = SCR;
    float* Q   = SCR + 600;
    float* K   = SCR + 1200;
    float* V   = SCR + 1800;
    float* O   = SCR + 2400;
    float* TMP = F1;
    float* mu  = MISC;
    float* rs  = MISC + 8;
    float* SC  = MISC + 16;
    float* ATT = MISC + 48;
    float* SEL = MISC + 80;
    float* RES = MISC + 192;
    float* part = MISC + 400;

    mha_stage(X, LNX, Q, K, V, O, mu, rs, SC, ATT, 3, 2, vWq, vWk, vWv, vWf, vg, vb, tid);

    for (int e = tid; e < 600; e += NTH) TMP[e] = X[e];
    __syncthreads();
    for (int e = tid; e < 600; e += NTH) {
        int r = e / 100, d = e - r * 100;
        int t = r / 3, v = r - t * 3;
        X[e] = TMP[(v * 2 + t) * 100 + d];
    }
    __syncthreads();

    mha_stage(X, LNX, Q, K, V, O, mu, rs, SC, ATT, 2, 3, mWq, mWk, mWv, mWf, mg, mb, tid);

    const int typ = edgetype[BSZ + b];
    if (tid < 100) {
        SEL[tid] = (X[(typ * 3 + 0) * 100 + tid] +
                    X[(typ * 3 + 1) * 100 + tid] +
                    X[(typ * 3 + 2) * 100 + tid]) * (1.0f / 3.0f);
    }
    __syncthreads();

    const int node = nodeids[b];
    for (int o = tid; o < 200; o += NTH) {
        float acc = 0.f;
        const float* rp = reflect + (size_t)typ * 100 * 200 + o;
        for (int d = 0; d < 100; d++) acc += SEL[d] * __ldg(rp + d * 200);
        RES[o] = base_embed[(size_t)node * 200 + o] + acc;
    }
    __syncthreads();
    float ps = 0.f;
    for (int o = tid; o < 200; o += NTH) ps += RES[o] * RES[o];
#pragma unroll
    for (int o2 = 16; o2; o2 >>= 1) ps += __shfl_xor_sync(0xffffffffu, ps, o2);
    if ((tid & 31) == 0) part[tid >> 5] = ps;
    __syncthreads();
    if (tid == 0) {
        float s = 0.f;
        for (int i = 0; i < 8; i++) s += part[i];
        part[0] = 1.0f / fmaxf(sqrtf(s), 1e-12f);
    }
    __syncthreads();
    float inv = part[0];
    for (int o = tid; o < 200; o += NTH) outp[(size_t)b * 200 + o] = RES[o] * inv;
}

// ---------------- host launcher ----------------
static void set_job(Job& j, const float* gsrc, float* out, const float* Ws, const float* Wn,
                    const int* neigh, int mode, int idx, int nseg,
                    const int* s, const int* fan, const int* noff,
                    int nb_b, int nb_t, int Rout, int Rin, int Tj, int blk0) {
    j.gsrc = gsrc; j.out = out; j.Ws = Ws; j.Wn = Wn; j.neigh = neigh;
    j.mode = mode; j.idx = idx; j.nseg = nseg;
    for (int i = 0; i < 5; i++) j.s[i] = s[i];
    for (int i = 0; i < 4; i++) j.fan[i] = fan[i];
    for (int i = 0; i < 5; i++) j.noff[i] = noff[i];
    j.nb_b = nb_b; j.nb_t = nb_t; j.Rout = Rout; j.Rin = Rin;
    j.rows = Rout * Tj; j.blk0 = blk0;
}

extern "C" void kernel_launch(void* const* d_in, const int* in_sizes, int n_in,
                              void* d_out, int out_size) {
    const int*   nodeids    = (const int*)d_in[0];
    const int*   edgetype   = (const int*)d_in[1];
    const int*   neighbors  = (const int*)d_in[2];
    const int*   rneigh     = (const int*)d_in[3];
    const float* base_embed = (const float*)d_in[4];
    const float* type_embed = (const float*)d_in[5];
    const float* rw_embed   = (const float*)d_in[6];
    const float* reflect    = (const float*)d_in[7];
    const float* agg0_self  = (const float*)d_in[8];
    const float* agg0_neigh = (const float*)d_in[9];
    const float* agg1_self  = (const float*)d_in[10];
    const float* agg1_neigh = (const float*)d_in[11];
    const float* rand_self  = (const float*)d_in[12];
    const float* rand_neighw= (const float*)d_in[13];
    const float* vWq = (const float*)d_in[14];
    const float* vWk = (const float*)d_in[15];
    const float* vWv = (const float*)d_in[16];
    const float* vWf = (const float*)d_in[17];
    const float* vg  = (const float*)d_in[18];
    const float* vb  = (const float*)d_in[19];
    const float* mWq = (const float*)d_in[20];
    const float* mWk = (const float*)d_in[21];
    const float* mWv = (const float*)d_in[22];
    const float* mWf = (const float*)d_in[23];
    const float* mg  = (const float*)d_in[24];
    const float* mb  = (const float*)d_in[25];
    float* outp = (float*)d_out;

    float* buf = nullptr;
    cudaGetSymbolAddress((void**)&buf, g_buf);

    cudaFuncSetAttribute(agg_multi_kernel,
                         cudaFuncAttributeMaxDynamicSharedMemorySize, AGG_SMEM_BYTES);
    cudaFuncSetAttribute(tail_kernel,
                         cudaFuncAttributeMaxDynamicSharedMemorySize, TK_SMEM_BYTES);

    const int s1[5]  = {1, 3, 15, 105, 945};
    const int f1[4]  = {3, 5, 7, 9};
    const int no1[5] = {0, 18, 21, 36, 141};
    const int s1b[5] = {1, 3, 15, 105, 0};
    const int f1b[4] = {3, 5, 7, 0};
    const int s0[5]  = {1, 3, 15, 0, 0};
    const int f0[4]  = {3, 5, 0, 0};
    const int no0[5] = {0, 0, 3, 0, 0};
    const int sT[5]  = {1, 3, 0, 0, 0};
    const int fT[4]  = {3, 0, 0, 0};
    const int noZ[5] = {0, 0, 0, 0, 0};

    MultiParams p;
    p.nodeids = nodeids;

    // ===== launch 1: all level-0 jobs =====
    {
        int b0 = 0;
        set_job(p.job[0], type_embed, buf + SCH1_L0, agg1_self, agg1_neigh, neighbors,
                1, 1, 4, s1, f1, no1, 2 * TOTAL_P, TOTAL_P, BSZ * 124, 0, 2, b0);
        b0 += (p.job[0].rows + 63) / 64;
        set_job(p.job[1], type_embed, buf + SCH0_L0, agg0_self, agg0_neigh, neighbors,
                1, 0, 2, s0, f0, no0, 2 * TOTAL_P, TOTAL_P, BSZ * 4, 0, 2, b0);
        b0 += (p.job[1].rows + 63) / 64;
        set_job(p.job[2], rw_embed, buf + RAND_L0, rand_self, rand_neighw, rneigh,
                2, 0, 2, s0, f0, no0, 18, 0, BSZ * 4, 0, 1, b0);
        b0 += (p.job[2].rows + 63) / 64;
        p.njobs = 3;
        agg_multi_kernel<<<b0, 160, AGG_SMEM_BYTES>>>(p);
    }
    // ===== launch 2: all level-1 jobs =====
    {
        int b0 = 0;
        set_job(p.job[0], buf + SCH1_L0, buf + SCH1_L1, agg1_self + 5000, agg1_neigh + 5000,
                nullptr, 0, 0, 3, s1b, f1b, noZ, 0, 0, BSZ * 19, BSZ * 124, 2, b0);
        b0 += (p.job[0].rows + 63) / 64;
        set_job(p.job[1], buf + SCH0_L0, buf + SPEC0, agg0_self + 5000, agg0_neigh + 5000,
                nullptr, 0, 0, 1, sT, fT, noZ, 0, 0, BSZ, BSZ * 4, 2, b0);
        b0 += (p.job[1].rows + 63) / 64;
        set_job(p.job[2], buf + RAND_L0, buf + RVIEW, rand_self + 5000, rand_neighw + 5000,
                nullptr, 0, 0, 1, sT, fT, noZ, 0, 0, BSZ, BSZ * 4, 1, b0);
        b0 += (p.job[2].rows + 63) / 64;
        p.njobs = 3;
        agg_multi_kernel<<<b0, 160, AGG_SMEM_BYTES>>>(p);
    }

    // ===== launch 3: fused tail =====
    tail_kernel<<<BSZ, NTH, TK_SMEM_BYTES>>>(
        buf + SCH1_L1, buf + SPEC0, buf + RVIEW,
        agg1_self, agg1_neigh,
        edgetype, nodeids, base_embed, reflect,
        vWq, vWk, vWv, vWf, vg, vb,
        mWq, mWk, mWv, mWf, mg, mb,
        outp);
}